// round 5
// baseline (speedup 1.0000x reference)
#include <cuda_runtime.h>
#include <cuda_bf16.h>
#include <cstdint>
#include <cstddef>

// ButterflyLayer1D: 9 chained batched GEMMs (M=65536, N=128, K in {128,256})
// via warp-level mma.sync bf16, split precision (hi+lo planes):
//   D = Ah*Wh + Al*Wh + Ah*Wl   (fp32 accum, residual ~2^-16)
// Activations live as separate bf16 hi/lo planes so the mainloop is pure
// cp.async double-buffered streaming; no conversion on the critical path.

#define SMEM_SWIZ(off) ((off) ^ (((off) >> 3) & 0x70))

__device__ __forceinline__ uint32_t smem_u32(const void* p) {
    uint32_t a;
    asm("{ .reg .u64 t; cvta.to.shared.u64 t, %1; cvt.u32.u64 %0, t; }" : "=r"(a) : "l"(p));
    return a;
}
__device__ __forceinline__ void ldsm_x4(uint32_t* r, uint32_t a) {
    asm volatile("ldmatrix.sync.aligned.m8n8.x4.shared.b16 {%0,%1,%2,%3}, [%4];"
        : "=r"(r[0]), "=r"(r[1]), "=r"(r[2]), "=r"(r[3]) : "r"(a));
}
__device__ __forceinline__ void mma_bf16(float* d, const uint32_t* a, const uint32_t* b) {
    asm volatile(
        "mma.sync.aligned.m16n8k16.row.col.f32.bf16.bf16.f32 "
        "{%0,%1,%2,%3}, {%4,%5,%6,%7}, {%8,%9}, {%0,%1,%2,%3};"
        : "+f"(d[0]), "+f"(d[1]), "+f"(d[2]), "+f"(d[3])
        : "r"(a[0]), "r"(a[1]), "r"(a[2]), "r"(a[3]), "r"(b[0]), "r"(b[1]));
}
__device__ __forceinline__ unsigned packbf(__nv_bfloat16 a, __nv_bfloat16 b) {
    return ((unsigned)__bfloat16_as_ushort(b) << 16) | (unsigned)__bfloat16_as_ushort(a);
}
#define CP_ASYNC16(dst, src) \
    asm volatile("cp.async.cg.shared.global [%0], [%1], 16;" :: "r"(dst), "l"(src))
#define CP_COMMIT() asm volatile("cp.async.commit_group;" ::: "memory")
#define CP_WAIT1()  asm volatile("cp.async.wait_group 1;" ::: "memory")

// ---------------- global scratch ----------------
#define ACT_ELEMS (1024 * 64 * 128)
__device__ unsigned short g_hiA[ACT_ELEMS];
__device__ unsigned short g_loA[ACT_ELEMS];
__device__ unsigned short g_hiB[ACT_ELEMS];
__device__ unsigned short g_loB[ACT_ELEMS];
#define WTOTAL 1998848
__device__ unsigned short g_whi_raw[WTOTAL];
__device__ unsigned short g_wlo_raw[WTOTAL];

// ---------------- weight prep: transpose + split to bf16 hi/lo ----------------
__global__ void prep_weights(const float* __restrict__ xf, const float* __restrict__ f1,
                             const float* __restrict__ f2, const float* __restrict__ f3,
                             const float* __restrict__ md, const float* __restrict__ f4,
                             const float* __restrict__ f5, const float* __restrict__ f6,
                             const float* __restrict__ kf)
{
    const int e = blockIdx.x * blockDim.x + threadIdx.x;
    if (e >= WTOTAL) return;
    const int off[10] = {0, 16384, 81920, 212992, 475136, 1523712, 1785856, 1916928, 1982464, WTOTAL};
    int t = 0;
    #pragma unroll
    for (int i = 1; i < 9; i++) if (e >= off[i]) t = i;
    const int K = (t == 0 || t == 4 || t == 8) ? 128 : 256;
    const float* src;
    switch (t) {
        case 0: src = xf; break; case 1: src = f1; break; case 2: src = f2; break;
        case 3: src = f3; break; case 4: src = md; break; case 5: src = f4; break;
        case 6: src = f5; break; case 7: src = f6; break; default: src = kf; break;
    }
    const int local = e - off[t];
    const int per = K * 128;
    const int g = local / per, rem = local % per;
    const int kk = rem >> 7, n = rem & 127;       // src [g][kk][n]
    const float v = src[local];
    const __nv_bfloat16 h = __float2bfloat16(v);
    const float lr = v - __bfloat162float(h);
    const int di = off[t] + g * per + n * K + kk; // dst [g][n][kk]
    g_whi_raw[di] = __bfloat16_as_ushort(h);
    g_wlo_raw[di] = __bfloat16_as_ushort(__float2bfloat16(lr));
}

// ---------------- stage kernel ----------------
// CTA tile 128x128, K chunks of 64, double-buffered cp.async pipeline.
// Per buffer: Ah/Al/Wh/Wl, each 128 rows x 128B (SW swizzled) = 64KB; 2 bufs.
#define BUF_BYTES 65536
#define DYN_SMEM  (2 * BUF_BYTES)

__global__ __launch_bounds__(256)
void stage_mma(const float* __restrict__ inF,
               const unsigned short* __restrict__ inHi, const unsigned short* __restrict__ inLo,
               const __nv_bfloat16* __restrict__ wh, const __nv_bfloat16* __restrict__ wl,
               const float* __restrict__ bias,
               float* __restrict__ outF, unsigned short* __restrict__ outHi,
               unsigned short* __restrict__ outLo,
               int stage, int p0, int p1, int tpg, int K)
{
    __shared__ int   sOff0[128];
    __shared__ int   sOff1[128];
    __shared__ int   sOutOff[128];
    __shared__ float sBias[128];
    extern __shared__ __align__(16) char dyn[];

    const int tid = threadIdx.x;
    const int lane = tid & 31, wid = tid >> 5;
    const int g    = blockIdx.x / tpg;
    const int tile = blockIdx.x % tpg;

    const size_t gstride = (size_t)K * 128;
    const __nv_bfloat16* whg = wh + (size_t)g * gstride;
    const __nv_bfloat16* wlg = wl + (size_t)g * gstride;

    // ---- per-row gather/scatter element offsets (proven indexing) ----
    if (tid < 128) {
        const int t = tile * 128 + tid;
        int r0 = 0, r1 = 0, o = 0;
        if (stage == 0 || stage == 4) {
            r0 = t * 128; r1 = r0;
            o  = t * 128;
        } else if (stage == 1) {                  // down
            const int n = t / p1, l = t % p1;
            int nb_in = p0 >> 1; if (nb_in == 0) nb_in = 1;
            r0 = ((n * nb_in + (g >> 1)) * (2 * p1) + 2 * l) * 128;
            r1 = r0 + 128;
            o  = ((n * p0 + g) * p1 + l) * 128;
        } else if (stage == 2) {                  // middle: g = k*8 + x
            const int n = t;
            const int k = g >> 3, x = g & 7;
            r0 = ((n * 8 + k) * 8 + x) * 128; r1 = r0;
            o  = ((n * 8 + x) * 8 + k) * 128;
        } else {                                  // up: g = 2x + j
            const int n = t / p1, l = t % p1;
            const int x = g >> 1, j = g & 1;
            const int nb_in = p0 * 2;
            r0 = ((n * nb_in + 2 * x)     * p1 + l) * 128;
            r1 = ((n * nb_in + 2 * x + 1) * p1 + l) * 128;
            o  = ((n * p0 + x) * (2 * p1) + 2 * l + j) * 128;
        }
        sOff0[tid] = r0; sOff1[tid] = r1; sOutOff[tid] = o;
        const float* bg = bias ? (bias + ((stage >= 1 && stage <= 3) ? g * 128 : 0)) : nullptr;
        sBias[tid] = bg ? bg[tid] : 0.0f;
    }
    __syncthreads();

    const uint32_t dynU = smem_u32(dyn);
    const bool f32in  = (stage == 0);
    const int  nk     = K >> 6;

    // ---- issue loads for chunk ch into buffer ch&1 ----
    auto issue_chunk = [&](int ch) {
        if (ch < nk) {
            char* base = dyn + (ch & 1) * BUF_BYTES;
            char* Ah = base; char* Al = base + 16384;
            char* Wh = base + 32768; char* Wl = base + 49152;
            const int k0 = ch << 6;
            const bool hi_half = (k0 < 128);
            const int  kk = hi_half ? k0 : (k0 - 128);
            if (f32in) {
                // A from fp32 x: register load + split + STS (stage 0 only)
                #pragma unroll
                for (int i = 0; i < 8; i++) {
                    const int s = tid + (i << 8);
                    const int row = s >> 4, q = s & 15;
                    const int off = (hi_half ? sOff0[row] : sOff1[row]) + kk + (q << 2);
                    const float4 v = *(const float4*)(inF + off);
                    const __nv_bfloat16 hx = __float2bfloat16(v.x), hy = __float2bfloat16(v.y);
                    const __nv_bfloat16 hz = __float2bfloat16(v.z), hw = __float2bfloat16(v.w);
                    const __nv_bfloat16 lx = __float2bfloat16(v.x - __bfloat162float(hx));
                    const __nv_bfloat16 ly = __float2bfloat16(v.y - __bfloat162float(hy));
                    const __nv_bfloat16 lz = __float2bfloat16(v.z - __bfloat162float(hz));
                    const __nv_bfloat16 lw = __float2bfloat16(v.w - __bfloat162float(hw));
                    const unsigned sw = SMEM_SWIZ((unsigned)(row * 128 + q * 8));
                    *(uint2*)(Ah + sw) = make_uint2(packbf(hx, hy), packbf(hz, hw));
                    *(uint2*)(Al + sw) = make_uint2(packbf(lx, ly), packbf(lz, lw));
                }
            } else {
                // A hi/lo via cp.async: 2 planes x 128 rows x 8 x 16B
                const uint32_t AhU = smem_u32(Ah), AlU = smem_u32(Al);
                #pragma unroll
                for (int i = 0; i < 8; i++) {
                    const int s = tid + (i << 8);
                    const int plane = s >> 10, row = (s >> 3) & 127, u = s & 7;
                    const int off = (hi_half ? sOff0[row] : sOff1[row]) + kk + (u << 3);
                    const unsigned short* src = (plane ? inLo : inHi) + off;
                    const uint32_t dst = (plane ? AlU : AhU) + SMEM_SWIZ((unsigned)(row * 128 + u * 16));
                    CP_ASYNC16(dst, src);
                }
            }
            // W hi/lo via cp.async: 2 planes x 128 n-rows x 8 x 16B
            {
                const uint32_t WhU = smem_u32(Wh), WlU = smem_u32(Wl);
                #pragma unroll
                for (int i = 0; i < 8; i++) {
                    const int s = tid + (i << 8);
                    const int plane = s >> 10, n = (s >> 3) & 127, u = s & 7;
                    const __nv_bfloat16* src = (plane ? wlg : whg) + (size_t)n * K + k0 + (u << 3);
                    const uint32_t dst = (plane ? WlU : WhU) + SMEM_SWIZ((unsigned)(n * 128 + u * 16));
                    CP_ASYNC16(dst, src);
                }
            }
        }
        CP_COMMIT();
    };

    // ---- warp tiling: 4x2 warps, each m32 x n64 ----
    const int warpM = wid >> 1, warpN = wid & 1;
    int offA[2], swA[2];
    #pragma unroll
    for (int mt = 0; mt < 2; mt++) {
        const int r = warpM * 32 + mt * 16 + ((lane & 8) ? 8 : 0) + (lane & 7);
        offA[mt] = r * 128; swA[mt] = (r & 7) << 4;
    }
    const int kaddA = (lane & 16) ? 16 : 0;
    int offB[4], swB[4];
    #pragma unroll
    for (int nt2 = 0; nt2 < 4; nt2++) {
        const int n = warpN * 64 + nt2 * 16 + ((lane & 16) ? 8 : 0) + (lane & 7);
        offB[nt2] = n * 128; swB[nt2] = (n & 7) << 4;
    }
    const int kaddB = (lane & 8) ? 16 : 0;

    float c[2][8][4];
    #pragma unroll
    for (int mt = 0; mt < 2; mt++)
        #pragma unroll
        for (int nt = 0; nt < 8; nt++)
            #pragma unroll
            for (int i = 0; i < 4; i++) c[mt][nt][i] = 0.0f;

    // ---- pipelined mainloop ----
    issue_chunk(0);
    for (int ch = 0; ch < nk; ch++) {
        issue_chunk(ch + 1);
        CP_WAIT1();
        __syncthreads();

        const uint32_t bufU = dynU + (ch & 1) * BUF_BYTES;
        const uint32_t AhU = bufU, AlU = bufU + 16384;
        const uint32_t WhU = bufU + 32768, WlU = bufU + 49152;
        #pragma unroll
        for (int ks = 0; ks < 4; ks++) {
            const int kb = ks * 32;
            uint32_t ah[2][4], al[2][4];
            #pragma unroll
            for (int mt = 0; mt < 2; mt++) {
                ldsm_x4(ah[mt], AhU + offA[mt] + ((kb + kaddA) ^ swA[mt]));
                ldsm_x4(al[mt], AlU + offA[mt] + ((kb + kaddA) ^ swA[mt]));
            }
            #pragma unroll
            for (int nt2 = 0; nt2 < 4; nt2++) {
                uint32_t bh[4], bl[4];
                ldsm_x4(bh, WhU + offB[nt2] + ((kb + kaddB) ^ swB[nt2]));
                ldsm_x4(bl, WlU + offB[nt2] + ((kb + kaddB) ^ swB[nt2]));
                #pragma unroll
                for (int mt = 0; mt < 2; mt++) {
                    #pragma unroll
                    for (int h = 0; h < 2; h++) {
                        float* cc = c[mt][nt2 * 2 + h];
                        mma_bf16(cc, ah[mt], bh + h * 2);
                        mma_bf16(cc, al[mt], bh + h * 2);
                        mma_bf16(cc, ah[mt], bl + h * 2);
                    }
                }
            }
        }
        __syncthreads();
    }

    // ---- epilogue: bias + relu, scatter (hi/lo planes or fp32 final) ----
    const bool doRelu = (stage != 4);
    const bool f32out = (stage == 4);
    #pragma unroll
    for (int mt = 0; mt < 2; mt++) {
        const int rbase = warpM * 32 + mt * 16 + (lane >> 2);
        #pragma unroll
        for (int h = 0; h < 2; h++) {
            const int off = sOutOff[rbase + h * 8];
            #pragma unroll
            for (int nt = 0; nt < 8; nt++) {
                const int col = warpN * 64 + nt * 8 + 2 * (lane & 3);
                float v0 = c[mt][nt][h * 2 + 0] + sBias[col];
                float v1 = c[mt][nt][h * 2 + 1] + sBias[col + 1];
                if (doRelu) { v0 = fmaxf(v0, 0.0f); v1 = fmaxf(v1, 0.0f); }
                if (f32out) {
                    float2 v; v.x = v0; v.y = v1;
                    *(float2*)(outF + off + col) = v;
                } else {
                    const __nv_bfloat16 h0 = __float2bfloat16(v0);
                    const __nv_bfloat16 h1 = __float2bfloat16(v1);
                    const __nv_bfloat16 l0 = __float2bfloat16(v0 - __bfloat162float(h0));
                    const __nv_bfloat16 l1 = __float2bfloat16(v1 - __bfloat162float(h1));
                    *(unsigned*)(outHi + off + col) = packbf(h0, h1);
                    *(unsigned*)(outLo + off + col) = packbf(l0, l1);
                }
            }
        }
    }
}

// ---------------- launch ----------------
extern "C" void kernel_launch(void* const* d_in, const int* in_sizes, int n_in,
                              void* d_out, int out_size)
{
    (void)in_sizes; (void)n_in; (void)out_size;
    const float* x  = (const float*)d_in[0];
    const float* xf = (const float*)d_in[1];
    const float* xb = (const float*)d_in[2];
    const float* f1 = (const float*)d_in[3];
    const float* b1 = (const float*)d_in[4];
    const float* f2 = (const float*)d_in[5];
    const float* b2 = (const float*)d_in[6];
    const float* f3 = (const float*)d_in[7];
    const float* b3 = (const float*)d_in[8];
    const float* md = (const float*)d_in[9];
    const float* mb = (const float*)d_in[10];
    const float* f4 = (const float*)d_in[11];
    const float* b4 = (const float*)d_in[12];
    const float* f5 = (const float*)d_in[13];
    const float* b5 = (const float*)d_in[14];
    const float* f6 = (const float*)d_in[15];
    const float* b6 = (const float*)d_in[16];
    const float* kf = (const float*)d_in[17];
    float* out = (float*)d_out;

    unsigned short *hA, *lA, *hB, *lB, *whiR, *wloR;
    cudaGetSymbolAddress((void**)&hA, g_hiA);
    cudaGetSymbolAddress((void**)&lA, g_loA);
    cudaGetSymbolAddress((void**)&hB, g_hiB);
    cudaGetSymbolAddress((void**)&lB, g_loB);
    cudaGetSymbolAddress((void**)&whiR, g_whi_raw);
    cudaGetSymbolAddress((void**)&wloR, g_wlo_raw);
    const __nv_bfloat16* whi = (const __nv_bfloat16*)whiR;
    const __nv_bfloat16* wlo = (const __nv_bfloat16*)wloR;

    cudaFuncSetAttribute(stage_mma, cudaFuncAttributeMaxDynamicSharedMemorySize, DYN_SMEM);

    prep_weights<<<(WTOTAL + 255) / 256, 256>>>(xf, f1, f2, f3, md, f4, f5, f6, kf);

    const int Oxf = 0, Of1 = 16384, Of2 = 81920, Of3 = 212992, Omd = 475136,
              Of4 = 1523712, Of5 = 1785856, Of6 = 1916928, Okf = 1982464;

    const dim3 grid(512), block(256);
    // (inF, inHi, inLo, wh, wl, bias, outF, outHi, outLo, stage, p0, p1, tpg, K)
    stage_mma<<<grid, block, DYN_SMEM>>>(x, nullptr, nullptr, whi + Oxf, wlo + Oxf, xb,
                                         nullptr, hA, lA, 0, 0, 0, 512, 128);
    stage_mma<<<grid, block, DYN_SMEM>>>(nullptr, hA, lA, whi + Of1, wlo + Of1, b1,
                                         nullptr, hB, lB, 1, 2, 32, 256, 256);
    stage_mma<<<grid, block, DYN_SMEM>>>(nullptr, hB, lB, whi + Of2, wlo + Of2, b2,
                                         nullptr, hA, lA, 1, 4, 16, 128, 256);
    stage_mma<<<grid, block, DYN_SMEM>>>(nullptr, hA, lA, whi + Of3, wlo + Of3, b3,
                                         nullptr, hB, lB, 1, 8, 8, 64, 256);
    stage_mma<<<grid, block, DYN_SMEM>>>(nullptr, hB, lB, whi + Omd, wlo + Omd, mb,
                                         nullptr, hA, lA, 2, 0, 0, 8, 128);
    stage_mma<<<grid, block, DYN_SMEM>>>(nullptr, hA, lA, whi + Of4, wlo + Of4, b4,
                                         nullptr, hB, lB, 3, 4, 8, 64, 256);
    stage_mma<<<grid, block, DYN_SMEM>>>(nullptr, hB, lB, whi + Of5, wlo + Of5, b5,
                                         nullptr, hA, lA, 3, 2, 16, 128, 256);
    stage_mma<<<grid, block, DYN_SMEM>>>(nullptr, hA, lA, whi + Of6, wlo + Of6, b6,
                                         nullptr, hB, lB, 3, 1, 32, 256, 256);
    stage_mma<<<grid, block, DYN_SMEM>>>(nullptr, hB, lB, whi + Okf, wlo + Okf, nullptr,
                                         out, nullptr, nullptr, 4, 0, 0, 512, 128);
}

// round 7
// speedup vs baseline: 1.1461x; 1.1461x over previous
#include <cuda_runtime.h>
#include <cuda_bf16.h>
#include <cstdint>
#include <cstddef>

// ButterflyLayer1D: 9 chained batched GEMMs (M=65536, N=128, K in {128,256})
// via warp-level mma.sync bf16, split precision (hi+lo planes):
//   D = Ah*Wh + Al*Wh + Ah*Wl   (fp32 accum, residual ~2^-16)
// K-chunks of 32 with SW64-swizzled 64B rows, 3-deep cp.async pipeline,
// 2 CTAs/SM (96KB dyn smem, 128 regs).

#define SW64(off) ((off) ^ (((off) >> 3) & 0x30))

__device__ __forceinline__ uint32_t smem_u32(const void* p) {
    uint32_t a;
    asm("{ .reg .u64 t; cvta.to.shared.u64 t, %1; cvt.u32.u64 %0, t; }" : "=r"(a) : "l"(p));
    return a;
}
__device__ __forceinline__ void ldsm_x4(uint32_t* r, uint32_t a) {
    asm volatile("ldmatrix.sync.aligned.m8n8.x4.shared.b16 {%0,%1,%2,%3}, [%4];"
        : "=r"(r[0]), "=r"(r[1]), "=r"(r[2]), "=r"(r[3]) : "r"(a));
}
__device__ __forceinline__ void mma_bf16(float* d, const uint32_t* a, const uint32_t* b) {
    asm volatile(
        "mma.sync.aligned.m16n8k16.row.col.f32.bf16.bf16.f32 "
        "{%0,%1,%2,%3}, {%4,%5,%6,%7}, {%8,%9}, {%0,%1,%2,%3};"
        : "+f"(d[0]), "+f"(d[1]), "+f"(d[2]), "+f"(d[3])
        : "r"(a[0]), "r"(a[1]), "r"(a[2]), "r"(a[3]), "r"(b[0]), "r"(b[1]));
}
__device__ __forceinline__ unsigned packbf(__nv_bfloat16 a, __nv_bfloat16 b) {
    return ((unsigned)__bfloat16_as_ushort(b) << 16) | (unsigned)__bfloat16_as_ushort(a);
}
#define CP_ASYNC16(dst, src) \
    asm volatile("cp.async.cg.shared.global [%0], [%1], 16;" :: "r"(dst), "l"(src))
#define CP_COMMIT() asm volatile("cp.async.commit_group;" ::: "memory")
#define CP_WAIT2()  asm volatile("cp.async.wait_group 2;" ::: "memory")

// ---------------- global scratch ----------------
#define ACT_ELEMS (1024 * 64 * 128)
__device__ unsigned short g_hiA[ACT_ELEMS];
__device__ unsigned short g_loA[ACT_ELEMS];
__device__ unsigned short g_hiB[ACT_ELEMS];
__device__ unsigned short g_loB[ACT_ELEMS];
#define WTOTAL 1998848
__device__ unsigned short g_whi_raw[WTOTAL];
__device__ unsigned short g_wlo_raw[WTOTAL];

// ---------------- weight prep: transpose + split to bf16 hi/lo ----------------
__global__ void prep_weights(const float* __restrict__ xf, const float* __restrict__ f1,
                             const float* __restrict__ f2, const float* __restrict__ f3,
                             const float* __restrict__ md, const float* __restrict__ f4,
                             const float* __restrict__ f5, const float* __restrict__ f6,
                             const float* __restrict__ kf)
{
    const int e = blockIdx.x * blockDim.x + threadIdx.x;
    if (e >= WTOTAL) return;
    const int off[10] = {0, 16384, 81920, 212992, 475136, 1523712, 1785856, 1916928, 1982464, WTOTAL};
    int t = 0;
    #pragma unroll
    for (int i = 1; i < 9; i++) if (e >= off[i]) t = i;
    const int K = (t == 0 || t == 4 || t == 8) ? 128 : 256;
    const float* src;
    switch (t) {
        case 0: src = xf; break; case 1: src = f1; break; case 2: src = f2; break;
        case 3: src = f3; break; case 4: src = md; break; case 5: src = f4; break;
        case 6: src = f5; break; case 7: src = f6; break; default: src = kf; break;
    }
    const int local = e - off[t];
    const int per = K * 128;
    const int g = local / per, rem = local % per;
    const int kk = rem >> 7, n = rem & 127;       // src [g][kk][n]
    const float v = src[local];
    const __nv_bfloat16 h = __float2bfloat16(v);
    const float lr = v - __bfloat162float(h);
    const int di = off[t] + g * per + n * K + kk; // dst [g][n][kk]
    g_whi_raw[di] = __bfloat16_as_ushort(h);
    g_wlo_raw[di] = __bfloat16_as_ushort(__float2bfloat16(lr));
}

// ---------------- stage kernel ----------------
// CTA tile 128x128, K chunks of 32, 3-deep cp.async pipeline.
// Per buffer: Ah/Al/Wh/Wl, each 128 rows x 64B (SW64) = 8KB -> 32KB; 3 bufs.
#define TILE_B   8192
#define BUF_BYTES 32768
#define NBUF 3
#define DYN_SMEM  (NBUF * BUF_BYTES)

__global__ __launch_bounds__(256, 2)
void stage_mma(const float* __restrict__ inF,
               const unsigned short* __restrict__ inHi, const unsigned short* __restrict__ inLo,
               const __nv_bfloat16* __restrict__ wh, const __nv_bfloat16* __restrict__ wl,
               const float* __restrict__ bias,
               float* __restrict__ outF, unsigned short* __restrict__ outHi,
               unsigned short* __restrict__ outLo,
               int stage, int p0, int p1, int tpg, int K)
{
    __shared__ int   sOff0[128];
    __shared__ int   sOff1[128];
    __shared__ int   sOutOff[128];
    __shared__ float sBias[128];
    extern __shared__ __align__(16) char dyn[];

    const int tid = threadIdx.x;
    const int lane = tid & 31, wid = tid >> 5;
    const int g    = blockIdx.x / tpg;
    const int tile = blockIdx.x % tpg;

    const size_t gstride = (size_t)K * 128;
    const __nv_bfloat16* whg = wh + (size_t)g * gstride;
    const __nv_bfloat16* wlg = wl + (size_t)g * gstride;

    // ---- per-row gather/scatter element offsets (proven indexing) ----
    if (tid < 128) {
        const int t = tile * 128 + tid;
        int r0 = 0, r1 = 0, o = 0;
        if (stage == 0 || stage == 4) {
            r0 = t * 128; r1 = r0;
            o  = t * 128;
        } else if (stage == 1) {                  // down
            const int n = t / p1, l = t % p1;
            int nb_in = p0 >> 1; if (nb_in == 0) nb_in = 1;
            r0 = ((n * nb_in + (g >> 1)) * (2 * p1) + 2 * l) * 128;
            r1 = r0 + 128;
            o  = ((n * p0 + g) * p1 + l) * 128;
        } else if (stage == 2) {                  // middle: g = k*8 + x
            const int n = t;
            const int k = g >> 3, x = g & 7;
            r0 = ((n * 8 + k) * 8 + x) * 128; r1 = r0;
            o  = ((n * 8 + x) * 8 + k) * 128;
        } else {                                  // up: g = 2x + j
            const int n = t / p1, l = t % p1;
            const int x = g >> 1, j = g & 1;
            const int nb_in = p0 * 2;
            r0 = ((n * nb_in + 2 * x)     * p1 + l) * 128;
            r1 = ((n * nb_in + 2 * x + 1) * p1 + l) * 128;
            o  = ((n * p0 + x) * (2 * p1) + 2 * l + j) * 128;
        }
        sOff0[tid] = r0; sOff1[tid] = r1; sOutOff[tid] = o;
        const float* bg = bias ? (bias + ((stage >= 1 && stage <= 3) ? g * 128 : 0)) : nullptr;
        sBias[tid] = bg ? bg[tid] : 0.0f;
    }
    __syncthreads();

    const uint32_t dynU = smem_u32(dyn);
    const bool f32in  = (stage == 0);
    const int  nk     = K >> 5;                   // chunks of 32

    // ---- issue loads for chunk ch into buffer ch%3 ----
    auto issue_chunk = [&](int ch) {
        if (ch < nk) {
            const int bufo = (ch % NBUF) * BUF_BYTES;
            const int k0 = ch << 5;
            const bool hi_half = (k0 < 128);
            const int  kk = hi_half ? k0 : (k0 - 128);
            if (f32in) {
                // A from fp32 x: load + split + STS (stage 0 only)
                char* Ah = dyn + bufo; char* Al = dyn + bufo + TILE_B;
                #pragma unroll
                for (int i = 0; i < 4; i++) {
                    const int s = tid + (i << 8);
                    const int row = s >> 3, q = s & 7;
                    const int off = sOff0[row] + kk + (q << 2);
                    const float4 v = *(const float4*)(inF + off);
                    const __nv_bfloat16 hx = __float2bfloat16(v.x), hy = __float2bfloat16(v.y);
                    const __nv_bfloat16 hz = __float2bfloat16(v.z), hw = __float2bfloat16(v.w);
                    const __nv_bfloat16 lx = __float2bfloat16(v.x - __bfloat162float(hx));
                    const __nv_bfloat16 ly = __float2bfloat16(v.y - __bfloat162float(hy));
                    const __nv_bfloat16 lz = __float2bfloat16(v.z - __bfloat162float(hz));
                    const __nv_bfloat16 lw = __float2bfloat16(v.w - __bfloat162float(hw));
                    const unsigned sw = SW64((unsigned)(row * 64 + q * 8));
                    *(uint2*)(Ah + sw) = make_uint2(packbf(hx, hy), packbf(hz, hw));
                    *(uint2*)(Al + sw) = make_uint2(packbf(lx, ly), packbf(lz, lw));
                }
            } else {
                // A hi/lo via cp.async: 2 planes x 128 rows x 4 x 16B
                const uint32_t AhU = dynU + bufo, AlU = dynU + bufo + TILE_B;
                #pragma unroll
                for (int i = 0; i < 4; i++) {
                    const int s = tid + (i << 8);
                    const int plane = s >> 9, row = (s >> 2) & 127, u = s & 3;
                    const int off = (hi_half ? sOff0[row] : sOff1[row]) + kk + (u << 3);
                    const unsigned short* src = (plane ? inLo : inHi) + off;
                    const uint32_t dst = (plane ? AlU : AhU) + SW64((unsigned)(row * 64 + u * 16));
                    CP_ASYNC16(dst, src);
                }
            }
            // W hi/lo via cp.async: 2 planes x 128 n-rows x 4 x 16B
            {
                const uint32_t WhU = dynU + bufo + 2 * TILE_B, WlU = dynU + bufo + 3 * TILE_B;
                #pragma unroll
                for (int i = 0; i < 4; i++) {
                    const int s = tid + (i << 8);
                    const int plane = s >> 9, n = (s >> 2) & 127, u = s & 3;
                    const __nv_bfloat16* src = (plane ? wlg : whg) + (size_t)n * K + k0 + (u << 3);
                    const uint32_t dst = (plane ? WlU : WhU) + SW64((unsigned)(n * 64 + u * 16));
                    CP_ASYNC16(dst, src);
                }
            }
        }
        CP_COMMIT();
    };

    // ---- warp tiling: 4x2 warps, each m32 x n64 ----
    const int warpM = wid >> 1, warpN = wid & 1;
    int offA[2], swA[2];
    #pragma unroll
    for (int mt = 0; mt < 2; mt++) {
        const int r = warpM * 32 + mt * 16 + ((lane & 8) ? 8 : 0) + (lane & 7);
        offA[mt] = r * 64; swA[mt] = ((r >> 1) & 3) << 4;
    }
    const int kaddA = (lane & 16) ? 16 : 0;
    int offB[4], swB[4];
    #pragma unroll
    for (int nt2 = 0; nt2 < 4; nt2++) {
        const int n = warpN * 64 + nt2 * 16 + ((lane & 16) ? 8 : 0) + (lane & 7);
        offB[nt2] = n * 64; swB[nt2] = ((n >> 1) & 3) << 4;
    }
    const int kaddB = (lane & 8) ? 16 : 0;

    float c[2][8][4];
    #pragma unroll
    for (int mt = 0; mt < 2; mt++)
        #pragma unroll
        for (int nt = 0; nt < 8; nt++)
            #pragma unroll
            for (int i = 0; i < 4; i++) c[mt][nt][i] = 0.0f;

    // ---- pipelined mainloop (3-deep) ----
    issue_chunk(0);
    issue_chunk(1);
    for (int ch = 0; ch < nk; ch++) {
        issue_chunk(ch + 2);
        CP_WAIT2();
        __syncthreads();

        const uint32_t bufU = dynU + (ch % NBUF) * BUF_BYTES;
        const uint32_t AhU = bufU, AlU = bufU + TILE_B;
        const uint32_t WhU = bufU + 2 * TILE_B, WlU = bufU + 3 * TILE_B;
        #pragma unroll
        for (int ks = 0; ks < 2; ks++) {
            const int kb = ks * 32;
            uint32_t ah[2][4], al[2][4];
            #pragma unroll
            for (int mt = 0; mt < 2; mt++) {
                ldsm_x4(ah[mt], AhU + offA[mt] + ((kb + kaddA) ^ swA[mt]));
                ldsm_x4(al[mt], AlU + offA[mt] + ((kb + kaddA) ^ swA[mt]));
            }
            #pragma unroll
            for (int nt2 = 0; nt2 < 4; nt2++) {
                uint32_t bh[4], bl[4];
                ldsm_x4(bh, WhU + offB[nt2] + ((kb + kaddB) ^ swB[nt2]));
                ldsm_x4(bl, WlU + offB[nt2] + ((kb + kaddB) ^ swB[nt2]));
                #pragma unroll
                for (int mt = 0; mt < 2; mt++) {
                    #pragma unroll
                    for (int h = 0; h < 2; h++) {
                        float* cc = c[mt][nt2 * 2 + h];
                        mma_bf16(cc, ah[mt], bh + h * 2);
                        mma_bf16(cc, al[mt], bh + h * 2);
                        mma_bf16(cc, ah[mt], bl + h * 2);
                    }
                }
            }
        }
        __syncthreads();
    }

    // ---- epilogue: bias + relu, scatter (hi/lo planes or fp32 final) ----
    const bool doRelu = (stage != 4);
    const bool f32out = (stage == 4);
    #pragma unroll
    for (int mt = 0; mt < 2; mt++) {
        const int rbase = warpM * 32 + mt * 16 + (lane >> 2);
        #pragma unroll
        for (int h = 0; h < 2; h++) {
            const int off = sOutOff[rbase + h * 8];
            #pragma unroll
            for (int nt = 0; nt < 8; nt++) {
                const int col = warpN * 64 + nt * 8 + 2 * (lane & 3);
                float v0 = c[mt][nt][h * 2 + 0] + sBias[col];
                float v1 = c[mt][nt][h * 2 + 1] + sBias[col + 1];
                if (doRelu) { v0 = fmaxf(v0, 0.0f); v1 = fmaxf(v1, 0.0f); }
                if (f32out) {
                    float2 v; v.x = v0; v.y = v1;
                    *(float2*)(outF + off + col) = v;
                } else {
                    const __nv_bfloat16 h0 = __float2bfloat16(v0);
                    const __nv_bfloat16 h1 = __float2bfloat16(v1);
                    const __nv_bfloat16 l0 = __float2bfloat16(v0 - __bfloat162float(h0));
                    const __nv_bfloat16 l1 = __float2bfloat16(v1 - __bfloat162float(h1));
                    *(unsigned*)(outHi + off + col) = packbf(h0, h1);
                    *(unsigned*)(outLo + off + col) = packbf(l0, l1);
                }
            }
        }
    }
}

// ---------------- launch ----------------
extern "C" void kernel_launch(void* const* d_in, const int* in_sizes, int n_in,
                              void* d_out, int out_size)
{
    (void)in_sizes; (void)n_in; (void)out_size;
    const float* x  = (const float*)d_in[0];
    const float* xf = (const float*)d_in[1];
    const float* xb = (const float*)d_in[2];
    const float* f1 = (const float*)d_in[3];
    const float* b1 = (const float*)d_in[4];
    const float* f2 = (const float*)d_in[5];
    const float* b2 = (const float*)d_in[6];
    const float* f3 = (const float*)d_in[7];
    const float* b3 = (const float*)d_in[8];
    const float* md = (const float*)d_in[9];
    const float* mb = (const float*)d_in[10];
    const float* f4 = (const float*)d_in[11];
    const float* b4 = (const float*)d_in[12];
    const float* f5 = (const float*)d_in[13];
    const float* b5 = (const float*)d_in[14];
    const float* f6 = (const float*)d_in[15];
    const float* b6 = (const float*)d_in[16];
    const float* kf = (const float*)d_in[17];
    float* out = (float*)d_out;

    unsigned short *hA, *lA, *hB, *lB, *whiR, *wloR;
    cudaGetSymbolAddress((void**)&hA, g_hiA);
    cudaGetSymbolAddress((void**)&lA, g_loA);
    cudaGetSymbolAddress((void**)&hB, g_hiB);
    cudaGetSymbolAddress((void**)&lB, g_loB);
    cudaGetSymbolAddress((void**)&whiR, g_whi_raw);
    cudaGetSymbolAddress((void**)&wloR, g_wlo_raw);
    const __nv_bfloat16* whi = (const __nv_bfloat16*)whiR;
    const __nv_bfloat16* wlo = (const __nv_bfloat16*)wloR;

    cudaFuncSetAttribute(stage_mma, cudaFuncAttributeMaxDynamicSharedMemorySize, DYN_SMEM);

    prep_weights<<<(WTOTAL + 255) / 256, 256>>>(xf, f1, f2, f3, md, f4, f5, f6, kf);

    const int Oxf = 0, Of1 = 16384, Of2 = 81920, Of3 = 212992, Omd = 475136,
              Of4 = 1523712, Of5 = 1785856, Of6 = 1916928, Okf = 1982464;

    const dim3 grid(512), block(256);
    // (inF, inHi, inLo, wh, wl, bias, outF, outHi, outLo, stage, p0, p1, tpg, K)
    stage_mma<<<grid, block, DYN_SMEM>>>(x, nullptr, nullptr, whi + Oxf, wlo + Oxf, xb,
                                         nullptr, hA, lA, 0, 0, 0, 512, 128);
    stage_mma<<<grid, block, DYN_SMEM>>>(nullptr, hA, lA, whi + Of1, wlo + Of1, b1,
                                         nullptr, hB, lB, 1, 2, 32, 256, 256);
    stage_mma<<<grid, block, DYN_SMEM>>>(nullptr, hB, lB, whi + Of2, wlo + Of2, b2,
                                         nullptr, hA, lA, 1, 4, 16, 128, 256);
    stage_mma<<<grid, block, DYN_SMEM>>>(nullptr, hA, lA, whi + Of3, wlo + Of3, b3,
                                         nullptr, hB, lB, 1, 8, 8, 64, 256);
    stage_mma<<<grid, block, DYN_SMEM>>>(nullptr, hB, lB, whi + Omd, wlo + Omd, mb,
                                         nullptr, hA, lA, 2, 0, 0, 8, 128);
    stage_mma<<<grid, block, DYN_SMEM>>>(nullptr, hA, lA, whi + Of4, wlo + Of4, b4,
                                         nullptr, hB, lB, 3, 4, 8, 64, 256);
    stage_mma<<<grid, block, DYN_SMEM>>>(nullptr, hB, lB, whi + Of5, wlo + Of5, b5,
                                         nullptr, hA, lA, 3, 2, 16, 128, 256);
    stage_mma<<<grid, block, DYN_SMEM>>>(nullptr, hA, lA, whi + Of6, wlo + Of6, b6,
                                         nullptr, hB, lB, 3, 1, 32, 256, 256);
    stage_mma<<<grid, block, DYN_SMEM>>>(nullptr, hB, lB, whi + Okf, wlo + Okf, nullptr,
                                         out, nullptr, nullptr, 4, 0, 0, 512, 128);
}

// round 9
// speedup vs baseline: 1.1556x; 1.0083x over previous
#include <cuda_runtime.h>
#include <cuda_bf16.h>
#include <cstdint>
#include <cstddef>

// ButterflyLayer1D: 9 chained batched GEMMs (M=65536, N=128, K in {128,256})
// via warp-level mma.sync bf16, split precision (hi+lo planes):
//   D = Ah*Wh + Al*Wh + Ah*Wl   (fp32 accum, residual ~2^-16)
// K-chunks of 32, SW64 swizzle, 3-buffer cp.async pipeline with ONE sync per
// chunk, MMAs interleaved by split-term for 4-way dependency-chain ILP.

#define SW64(off) ((off) ^ (((off) >> 3) & 0x30))

__device__ __forceinline__ uint32_t smem_u32(const void* p) {
    uint32_t a;
    asm("{ .reg .u64 t; cvta.to.shared.u64 t, %1; cvt.u32.u64 %0, t; }" : "=r"(a) : "l"(p));
    return a;
}
__device__ __forceinline__ void ldsm_x4(uint32_t* r, uint32_t a) {
    asm volatile("ldmatrix.sync.aligned.m8n8.x4.shared.b16 {%0,%1,%2,%3}, [%4];"
        : "=r"(r[0]), "=r"(r[1]), "=r"(r[2]), "=r"(r[3]) : "r"(a));
}
__device__ __forceinline__ void mma_bf16(float* d, const uint32_t* a, const uint32_t* b) {
    asm volatile(
        "mma.sync.aligned.m16n8k16.row.col.f32.bf16.bf16.f32 "
        "{%0,%1,%2,%3}, {%4,%5,%6,%7}, {%8,%9}, {%0,%1,%2,%3};"
        : "+f"(d[0]), "+f"(d[1]), "+f"(d[2]), "+f"(d[3])
        : "r"(a[0]), "r"(a[1]), "r"(a[2]), "r"(a[3]), "r"(b[0]), "r"(b[1]));
}
__device__ __forceinline__ unsigned packbf(__nv_bfloat16 a, __nv_bfloat16 b) {
    return ((unsigned)__bfloat16_as_ushort(b) << 16) | (unsigned)__bfloat16_as_ushort(a);
}
#define CP_ASYNC16(dst, src) \
    asm volatile("cp.async.cg.shared.global [%0], [%1], 16;" :: "r"(dst), "l"(src))
#define CP_COMMIT() asm volatile("cp.async.commit_group;" ::: "memory")
#define CP_WAIT1()  asm volatile("cp.async.wait_group 1;" ::: "memory")

// ---------------- global scratch ----------------
#define ACT_ELEMS (1024 * 64 * 128)
__device__ unsigned short g_hiA[ACT_ELEMS];
__device__ unsigned short g_loA[ACT_ELEMS];
__device__ unsigned short g_hiB[ACT_ELEMS];
__device__ unsigned short g_loB[ACT_ELEMS];
#define WTOTAL 1998848
__device__ unsigned short g_whi_raw[WTOTAL];
__device__ unsigned short g_wlo_raw[WTOTAL];

// ---------------- weight prep: transpose + split to bf16 hi/lo ----------------
__global__ void prep_weights(const float* __restrict__ xf, const float* __restrict__ f1,
                             const float* __restrict__ f2, const float* __restrict__ f3,
                             const float* __restrict__ md, const float* __restrict__ f4,
                             const float* __restrict__ f5, const float* __restrict__ f6,
                             const float* __restrict__ kf)
{
    const int e = blockIdx.x * blockDim.x + threadIdx.x;
    if (e >= WTOTAL) return;
    const int off[10] = {0, 16384, 81920, 212992, 475136, 1523712, 1785856, 1916928, 1982464, WTOTAL};
    int t = 0;
    #pragma unroll
    for (int i = 1; i < 9; i++) if (e >= off[i]) t = i;
    const int K = (t == 0 || t == 4 || t == 8) ? 128 : 256;
    const float* src;
    switch (t) {
        case 0: src = xf; break; case 1: src = f1; break; case 2: src = f2; break;
        case 3: src = f3; break; case 4: src = md; break; case 5: src = f4; break;
        case 6: src = f5; break; case 7: src = f6; break; default: src = kf; break;
    }
    const int local = e - off[t];
    const int per = K * 128;
    const int g = local / per, rem = local % per;
    const int kk = rem >> 7, n = rem & 127;       // src [g][kk][n]
    const float v = src[local];
    const __nv_bfloat16 h = __float2bfloat16(v);
    const float lr = v - __bfloat162float(h);
    const int di = off[t] + g * per + n * K + kk; // dst [g][n][kk]
    g_whi_raw[di] = __bfloat16_as_ushort(h);
    g_wlo_raw[di] = __bfloat16_as_ushort(__float2bfloat16(lr));
}

// ---------------- stage kernel ----------------
// CTA tile 128x128, K chunks of 32, 3-buffer cp.async pipeline (depth 2).
// Per buffer: Ah/Al/Wh/Wl, each 128 rows x 64B (SW64) = 8KB -> 32KB; 3 bufs.
#define TILE_B   8192
#define BUF_BYTES 32768
#define NBUF 3
#define DYN_SMEM  (NBUF * BUF_BYTES)

__global__ __launch_bounds__(256, 2)
void stage_mma(const float* __restrict__ inF,
               const unsigned short* __restrict__ inHi, const unsigned short* __restrict__ inLo,
               const __nv_bfloat16* __restrict__ wh, const __nv_bfloat16* __restrict__ wl,
               const float* __restrict__ bias,
               float* __restrict__ outF, unsigned short* __restrict__ outHi,
               unsigned short* __restrict__ outLo,
               int stage, int p0, int p1, int tpg, int K)
{
    __shared__ int   sOff0[128];
    __shared__ int   sOff1[128];
    __shared__ int   sOutOff[128];
    __shared__ float sBias[128];
    extern __shared__ __align__(16) char dyn[];

    const int tid = threadIdx.x;
    const int lane = tid & 31, wid = tid >> 5;
    const int g    = blockIdx.x / tpg;
    const int tile = blockIdx.x % tpg;

    const size_t gstride = (size_t)K * 128;
    const __nv_bfloat16* whg = wh + (size_t)g * gstride;
    const __nv_bfloat16* wlg = wl + (size_t)g * gstride;

    // ---- per-row gather/scatter element offsets (proven indexing) ----
    if (tid < 128) {
        const int t = tile * 128 + tid;
        int r0 = 0, r1 = 0, o = 0;
        if (stage == 0 || stage == 4) {
            r0 = t * 128; r1 = r0;
            o  = t * 128;
        } else if (stage == 1) {                  // down
            const int n = t / p1, l = t % p1;
            int nb_in = p0 >> 1; if (nb_in == 0) nb_in = 1;
            r0 = ((n * nb_in + (g >> 1)) * (2 * p1) + 2 * l) * 128;
            r1 = r0 + 128;
            o  = ((n * p0 + g) * p1 + l) * 128;
        } else if (stage == 2) {                  // middle: g = k*8 + x
            const int n = t;
            const int k = g >> 3, x = g & 7;
            r0 = ((n * 8 + k) * 8 + x) * 128; r1 = r0;
            o  = ((n * 8 + x) * 8 + k) * 128;
        } else {                                  // up: g = 2x + j
            const int n = t / p1, l = t % p1;
            const int x = g >> 1, j = g & 1;
            const int nb_in = p0 * 2;
            r0 = ((n * nb_in + 2 * x)     * p1 + l) * 128;
            r1 = ((n * nb_in + 2 * x + 1) * p1 + l) * 128;
            o  = ((n * p0 + x) * (2 * p1) + 2 * l + j) * 128;
        }
        sOff0[tid] = r0; sOff1[tid] = r1; sOutOff[tid] = o;
        const float* bg = bias ? (bias + ((stage >= 1 && stage <= 3) ? g * 128 : 0)) : nullptr;
        sBias[tid] = bg ? bg[tid] : 0.0f;
    }
    __syncthreads();

    const uint32_t dynU = smem_u32(dyn);
    const bool f32in  = (stage == 0);
    const int  nk     = K >> 5;                   // chunks of 32

    // ---- issue loads for chunk ch into buffer ch%3 ----
    auto issue_chunk = [&](int ch) {
        if (ch < nk) {
            const int bufo = (ch % NBUF) * BUF_BYTES;
            const int k0 = ch << 5;
            const bool hi_half = (k0 < 128);
            const int  kk = hi_half ? k0 : (k0 - 128);
            if (f32in) {
                // A from fp32 x: load + split + STS (stage 0 only)
                char* Ah = dyn + bufo; char* Al = dyn + bufo + TILE_B;
                #pragma unroll
                for (int i = 0; i < 4; i++) {
                    const int s = tid + (i << 8);
                    const int row = s >> 3, q = s & 7;
                    const int off = sOff0[row] + kk + (q << 2);
                    const float4 v = *(const float4*)(inF + off);
                    const __nv_bfloat16 hx = __float2bfloat16(v.x), hy = __float2bfloat16(v.y);
                    const __nv_bfloat16 hz = __float2bfloat16(v.z), hw = __float2bfloat16(v.w);
                    const __nv_bfloat16 lx = __float2bfloat16(v.x - __bfloat162float(hx));
                    const __nv_bfloat16 ly = __float2bfloat16(v.y - __bfloat162float(hy));
                    const __nv_bfloat16 lz = __float2bfloat16(v.z - __bfloat162float(hz));
                    const __nv_bfloat16 lw = __float2bfloat16(v.w - __bfloat162float(hw));
                    const unsigned sw = SW64((unsigned)(row * 64 + q * 8));
                    *(uint2*)(Ah + sw) = make_uint2(packbf(hx, hy), packbf(hz, hw));
                    *(uint2*)(Al + sw) = make_uint2(packbf(lx, ly), packbf(lz, lw));
                }
            } else {
                // A hi/lo via cp.async: 2 planes x 128 rows x 4 x 16B
                const uint32_t AhU = dynU + bufo, AlU = dynU + bufo + TILE_B;
                #pragma unroll
                for (int i = 0; i < 4; i++) {
                    const int s = tid + (i << 8);
                    const int plane = s >> 9, row = (s >> 2) & 127, u = s & 3;
                    const int off = (hi_half ? sOff0[row] : sOff1[row]) + kk + (u << 3);
                    const unsigned short* src = (plane ? inLo : inHi) + off;
                    const uint32_t dst = (plane ? AlU : AhU) + SW64((unsigned)(row * 64 + u * 16));
                    CP_ASYNC16(dst, src);
                }
            }
            // W hi/lo via cp.async: 2 planes x 128 n-rows x 4 x 16B
            {
                const uint32_t WhU = dynU + bufo + 2 * TILE_B, WlU = dynU + bufo + 3 * TILE_B;
                #pragma unroll
                for (int i = 0; i < 4; i++) {
                    const int s = tid + (i << 8);
                    const int plane = s >> 9, n = (s >> 2) & 127, u = s & 3;
                    const __nv_bfloat16* src = (plane ? wlg : whg) + (size_t)n * K + k0 + (u << 3);
                    const uint32_t dst = (plane ? WlU : WhU) + SW64((unsigned)(n * 64 + u * 16));
                    CP_ASYNC16(dst, src);
                }
            }
        }
        CP_COMMIT();
    };

    // ---- warp tiling: 4x2 warps, each m32 x n64 ----
    const int warpM = wid >> 1, warpN = wid & 1;
    int offA[2], swA[2];
    #pragma unroll
    for (int mt = 0; mt < 2; mt++) {
        const int r = warpM * 32 + mt * 16 + ((lane & 8) ? 8 : 0) + (lane & 7);
        offA[mt] = r * 64; swA[mt] = ((r >> 1) & 3) << 4;
    }
    const int kaddA = (lane & 16) ? 16 : 0;
    int offB[4], swB[4];
    #pragma unroll
    for (int nt2 = 0; nt2 < 4; nt2++) {
        const int n = warpN * 64 + nt2 * 16 + ((lane & 16) ? 8 : 0) + (lane & 7);
        offB[nt2] = n * 64; swB[nt2] = ((n >> 1) & 3) << 4;
    }
    const int kaddB = (lane & 8) ? 16 : 0;

    float c[2][8][4];
    #pragma unroll
    for (int mt = 0; mt < 2; mt++)
        #pragma unroll
        for (int nt = 0; nt < 8; nt++)
            #pragma unroll
            for (int i = 0; i < 4; i++) c[mt][nt][i] = 0.0f;

    // ---- pipelined mainloop: ONE sync per chunk (multistage order) ----
    issue_chunk(0);
    issue_chunk(1);
    for (int ch = 0; ch < nk; ch++) {
        CP_WAIT1();                                // chunk ch's group retired
        __syncthreads();                           // data visible; prev-buf reads done

        const uint32_t bufU = dynU + (ch % NBUF) * BUF_BYTES;
        const uint32_t AhU = bufU, AlU = bufU + TILE_B;
        const uint32_t WhU = bufU + 2 * TILE_B, WlU = bufU + 3 * TILE_B;
        #pragma unroll
        for (int ks = 0; ks < 2; ks++) {
            const int kb = ks * 32;
            uint32_t ah[2][4], al[2][4];
            #pragma unroll
            for (int mt = 0; mt < 2; mt++) {
                ldsm_x4(ah[mt], AhU + offA[mt] + ((kb + kaddA) ^ swA[mt]));
                ldsm_x4(al[mt], AlU + offA[mt] + ((kb + kaddA) ^ swA[mt]));
            }
            #pragma unroll
            for (int nt2 = 0; nt2 < 4; nt2++) {
                uint32_t bh[4], bl[4];
                ldsm_x4(bh, WhU + offB[nt2] + ((kb + kaddB) ^ swB[nt2]));
                ldsm_x4(bl, WlU + offB[nt2] + ((kb + kaddB) ^ swB[nt2]));
                float* c00 = c[0][nt2 * 2 + 0];
                float* c01 = c[0][nt2 * 2 + 1];
                float* c10 = c[1][nt2 * 2 + 0];
                float* c11 = c[1][nt2 * 2 + 1];
                // term Ah*Wh — 4 independent chains, round-robin
                mma_bf16(c00, ah[0], bh + 0); mma_bf16(c01, ah[0], bh + 2);
                mma_bf16(c10, ah[1], bh + 0); mma_bf16(c11, ah[1], bh + 2);
                // term Al*Wh
                mma_bf16(c00, al[0], bh + 0); mma_bf16(c01, al[0], bh + 2);
                mma_bf16(c10, al[1], bh + 0); mma_bf16(c11, al[1], bh + 2);
                // term Ah*Wl
                mma_bf16(c00, ah[0], bl + 0); mma_bf16(c01, ah[0], bl + 2);
                mma_bf16(c10, ah[1], bl + 0); mma_bf16(c11, ah[1], bl + 2);
            }
        }
        issue_chunk(ch + 2);                       // writes buf read at iter ch-1 (safe)
    }

    // ---- epilogue: bias + relu, scatter (hi/lo planes or fp32 final) ----
    const bool doRelu = (stage != 4);
    const bool f32out = (stage == 4);
    #pragma unroll
    for (int mt = 0; mt < 2; mt++) {
        const int rbase = warpM * 32 + mt * 16 + (lane >> 2);
        #pragma unroll
        for (int h = 0; h < 2; h++) {
            const int off = sOutOff[rbase + h * 8];
            #pragma unroll
            for (int nt = 0; nt < 8; nt++) {
                const int col = warpN * 64 + nt * 8 + 2 * (lane & 3);
                float v0 = c[mt][nt][h * 2 + 0] + sBias[col];
                float v1 = c[mt][nt][h * 2 + 1] + sBias[col + 1];
                if (doRelu) { v0 = fmaxf(v0, 0.0f); v1 = fmaxf(v1, 0.0f); }
                if (f32out) {
                    float2 v; v.x = v0; v.y = v1;
                    *(float2*)(outF + off + col) = v;
                } else {
                    const __nv_bfloat16 h0 = __float2bfloat16(v0);
                    const __nv_bfloat16 h1 = __float2bfloat16(v1);
                    const __nv_bfloat16 l0 = __float2bfloat16(v0 - __bfloat162float(h0));
                    const __nv_bfloat16 l1 = __float2bfloat16(v1 - __bfloat162float(h1));
                    *(unsigned*)(outHi + off + col) = packbf(h0, h1);
                    *(unsigned*)(outLo + off + col) = packbf(l0, l1);
                }
            }
        }
    }
}

// ---------------- launch ----------------
extern "C" void kernel_launch(void* const* d_in, const int* in_sizes, int n_in,
                              void* d_out, int out_size)
{
    (void)in_sizes; (void)n_in; (void)out_size;
    const float* x  = (const float*)d_in[0];
    const float* xf = (const float*)d_in[1];
    const float* xb = (const float*)d_in[2];
    const float* f1 = (const float*)d_in[3];
    const float* b1 = (const float*)d_in[4];
    const float* f2 = (const float*)d_in[5];
    const float* b2 = (const float*)d_in[6];
    const float* f3 = (const float*)d_in[7];
    const float* b3 = (const float*)d_in[8];
    const float* md = (const float*)d_in[9];
    const float* mb = (const float*)d_in[10];
    const float* f4 = (const float*)d_in[11];
    const float* b4 = (const float*)d_in[12];
    const float* f5 = (const float*)d_in[13];
    const float* b5 = (const float*)d_in[14];
    const float* f6 = (const float*)d_in[15];
    const float* b6 = (const float*)d_in[16];
    const float* kf = (const float*)d_in[17];
    float* out = (float*)d_out;

    unsigned short *hA, *lA, *hB, *lB, *whiR, *wloR;
    cudaGetSymbolAddress((void**)&hA, g_hiA);
    cudaGetSymbolAddress((void**)&lA, g_loA);
    cudaGetSymbolAddress((void**)&hB, g_hiB);
    cudaGetSymbolAddress((void**)&lB, g_loB);
    cudaGetSymbolAddress((void**)&whiR, g_whi_raw);
    cudaGetSymbolAddress((void**)&wloR, g_wlo_raw);
    const __nv_bfloat16* whi = (const __nv_bfloat16*)whiR;
    const __nv_bfloat16* wlo = (const __nv_bfloat16*)wloR;

    cudaFuncSetAttribute(stage_mma, cudaFuncAttributeMaxDynamicSharedMemorySize, DYN_SMEM);

    prep_weights<<<(WTOTAL + 255) / 256, 256>>>(xf, f1, f2, f3, md, f4, f5, f6, kf);

    const int Oxf = 0, Of1 = 16384, Of2 = 81920, Of3 = 212992, Omd = 475136,
              Of4 = 1523712, Of5 = 1785856, Of6 = 1916928, Okf = 1982464;

    const dim3 grid(512), block(256);
    // (inF, inHi, inLo, wh, wl, bias, outF, outHi, outLo, stage, p0, p1, tpg, K)
    stage_mma<<<grid, block, DYN_SMEM>>>(x, nullptr, nullptr, whi + Oxf, wlo + Oxf, xb,
                                         nullptr, hA, lA, 0, 0, 0, 512, 128);
    stage_mma<<<grid, block, DYN_SMEM>>>(nullptr, hA, lA, whi + Of1, wlo + Of1, b1,
                                         nullptr, hB, lB, 1, 2, 32, 256, 256);
    stage_mma<<<grid, block, DYN_SMEM>>>(nullptr, hB, lB, whi + Of2, wlo + Of2, b2,
                                         nullptr, hA, lA, 1, 4, 16, 128, 256);
    stage_mma<<<grid, block, DYN_SMEM>>>(nullptr, hA, lA, whi + Of3, wlo + Of3, b3,
                                         nullptr, hB, lB, 1, 8, 8, 64, 256);
    stage_mma<<<grid, block, DYN_SMEM>>>(nullptr, hB, lB, whi + Omd, wlo + Omd, mb,
                                         nullptr, hA, lA, 2, 0, 0, 8, 128);
    stage_mma<<<grid, block, DYN_SMEM>>>(nullptr, hA, lA, whi + Of4, wlo + Of4, b4,
                                         nullptr, hB, lB, 3, 4, 8, 64, 256);
    stage_mma<<<grid, block, DYN_SMEM>>>(nullptr, hB, lB, whi + Of5, wlo + Of5, b5,
                                         nullptr, hA, lA, 3, 2, 16, 128, 256);
    stage_mma<<<grid, block, DYN_SMEM>>>(nullptr, hA, lA, whi + Of6, wlo + Of6, b6,
                                         nullptr, hB, lB, 3, 1, 32, 256, 256);
    stage_mma<<<grid, block, DYN_SMEM>>>(nullptr, hB, lB, whi + Okf, wlo + Okf, nullptr,
                                         out, nullptr, nullptr, 4, 0, 0, 512, 128);
}

// round 12
// speedup vs baseline: 1.1620x; 1.0056x over previous
#include <cuda_runtime.h>
#include <cuda_bf16.h>
#include <cstdint>
#include <cstddef>

// ButterflyLayer1D: 9 chained batched GEMMs (M=65536, N=128, K in {128,256})
// via warp-level mma.sync bf16, split precision (hi+lo planes):
//   D = Ah*Wh + Al*Wh + Ah*Wl   (fp32 accum, residual ~2^-16)
// K-chunks of 32, SW64 swizzle, 3-buffer cp.async pipeline (R9 ordering),
// plus B-fragment ping-pong so each ldmatrix's latency is covered by the
// previous block's MMA issues.

#define SW64(off) ((off) ^ (((off) >> 3) & 0x30))

__device__ __forceinline__ uint32_t smem_u32(const void* p) {
    uint32_t a;
    asm("{ .reg .u64 t; cvta.to.shared.u64 t, %1; cvt.u32.u64 %0, t; }" : "=r"(a) : "l"(p));
    return a;
}
__device__ __forceinline__ void ldsm_x4(uint32_t* r, uint32_t a) {
    asm volatile("ldmatrix.sync.aligned.m8n8.x4.shared.b16 {%0,%1,%2,%3}, [%4];"
        : "=r"(r[0]), "=r"(r[1]), "=r"(r[2]), "=r"(r[3]) : "r"(a));
}
__device__ __forceinline__ void mma_bf16(float* d, const uint32_t* a, const uint32_t* b) {
    asm volatile(
        "mma.sync.aligned.m16n8k16.row.col.f32.bf16.bf16.f32 "
        "{%0,%1,%2,%3}, {%4,%5,%6,%7}, {%8,%9}, {%0,%1,%2,%3};"
        : "+f"(d[0]), "+f"(d[1]), "+f"(d[2]), "+f"(d[3])
        : "r"(a[0]), "r"(a[1]), "r"(a[2]), "r"(a[3]), "r"(b[0]), "r"(b[1]));
}
__device__ __forceinline__ unsigned packbf(__nv_bfloat16 a, __nv_bfloat16 b) {
    return ((unsigned)__bfloat16_as_ushort(b) << 16) | (unsigned)__bfloat16_as_ushort(a);
}
#define CP_ASYNC16(dst, src) \
    asm volatile("cp.async.cg.shared.global [%0], [%1], 16;" :: "r"(dst), "l"(src))
#define CP_COMMIT() asm volatile("cp.async.commit_group;" ::: "memory")
#define CP_WAIT1()  asm volatile("cp.async.wait_group 1;" ::: "memory")

// ---------------- global scratch ----------------
#define ACT_ELEMS (1024 * 64 * 128)
__device__ unsigned short g_hiA[ACT_ELEMS];
__device__ unsigned short g_loA[ACT_ELEMS];
__device__ unsigned short g_hiB[ACT_ELEMS];
__device__ unsigned short g_loB[ACT_ELEMS];
#define WTOTAL 1998848
__device__ unsigned short g_whi_raw[WTOTAL];
__device__ unsigned short g_wlo_raw[WTOTAL];

// ---------------- weight prep: transpose + split to bf16 hi/lo ----------------
__global__ void prep_weights(const float* __restrict__ xf, const float* __restrict__ f1,
                             const float* __restrict__ f2, const float* __restrict__ f3,
                             const float* __restrict__ md, const float* __restrict__ f4,
                             const float* __restrict__ f5, const float* __restrict__ f6,
                             const float* __restrict__ kf)
{
    const int e = blockIdx.x * blockDim.x + threadIdx.x;
    if (e >= WTOTAL) return;
    const int off[10] = {0, 16384, 81920, 212992, 475136, 1523712, 1785856, 1916928, 1982464, WTOTAL};
    int t = 0;
    #pragma unroll
    for (int i = 1; i < 9; i++) if (e >= off[i]) t = i;
    const int K = (t == 0 || t == 4 || t == 8) ? 128 : 256;
    const float* src;
    switch (t) {
        case 0: src = xf; break; case 1: src = f1; break; case 2: src = f2; break;
        case 3: src = f3; break; case 4: src = md; break; case 5: src = f4; break;
        case 6: src = f5; break; case 7: src = f6; break; default: src = kf; break;
    }
    const int local = e - off[t];
    const int per = K * 128;
    const int g = local / per, rem = local % per;
    const int kk = rem >> 7, n = rem & 127;       // src [g][kk][n]
    const float v = src[local];
    const __nv_bfloat16 h = __float2bfloat16(v);
    const float lr = v - __bfloat162float(h);
    const int di = off[t] + g * per + n * K + kk; // dst [g][n][kk]
    g_whi_raw[di] = __bfloat16_as_ushort(h);
    g_wlo_raw[di] = __bfloat16_as_ushort(__float2bfloat16(lr));
}

// ---------------- stage kernel ----------------
// CTA tile 128x128, K chunks of 32, 3-buffer cp.async pipeline (depth 2).
// Per buffer: Ah/Al/Wh/Wl, each 128 rows x 64B (SW64) = 8KB -> 32KB; 3 bufs.
#define TILE_B   8192
#define BUF_BYTES 32768
#define NBUF 3
#define DYN_SMEM  (NBUF * BUF_BYTES)

__global__ __launch_bounds__(256, 2)
void stage_mma(const float* __restrict__ inF,
               const unsigned short* __restrict__ inHi, const unsigned short* __restrict__ inLo,
               const __nv_bfloat16* __restrict__ wh, const __nv_bfloat16* __restrict__ wl,
               const float* __restrict__ bias,
               float* __restrict__ outF, unsigned short* __restrict__ outHi,
               unsigned short* __restrict__ outLo,
               int stage, int p0, int p1, int tpg, int K)
{
    __shared__ int   sOff0[128];
    __shared__ int   sOff1[128];
    __shared__ int   sOutOff[128];
    __shared__ float sBias[128];
    extern __shared__ __align__(16) char dyn[];

    const int tid = threadIdx.x;
    const int lane = tid & 31, wid = tid >> 5;
    const int g    = blockIdx.x / tpg;
    const int tile = blockIdx.x % tpg;

    const size_t gstride = (size_t)K * 128;
    const __nv_bfloat16* whg = wh + (size_t)g * gstride;
    const __nv_bfloat16* wlg = wl + (size_t)g * gstride;

    // ---- per-row gather/scatter element offsets (proven indexing) ----
    if (tid < 128) {
        const int t = tile * 128 + tid;
        int r0 = 0, r1 = 0, o = 0;
        if (stage == 0 || stage == 4) {
            r0 = t * 128; r1 = r0;
            o  = t * 128;
        } else if (stage == 1) {                  // down
            const int n = t / p1, l = t % p1;
            int nb_in = p0 >> 1; if (nb_in == 0) nb_in = 1;
            r0 = ((n * nb_in + (g >> 1)) * (2 * p1) + 2 * l) * 128;
            r1 = r0 + 128;
            o  = ((n * p0 + g) * p1 + l) * 128;
        } else if (stage == 2) {                  // middle: g = k*8 + x
            const int n = t;
            const int k = g >> 3, x = g & 7;
            r0 = ((n * 8 + k) * 8 + x) * 128; r1 = r0;
            o  = ((n * 8 + x) * 8 + k) * 128;
        } else {                                  // up: g = 2x + j
            const int n = t / p1, l = t % p1;
            const int x = g >> 1, j = g & 1;
            const int nb_in = p0 * 2;
            r0 = ((n * nb_in + 2 * x)     * p1 + l) * 128;
            r1 = ((n * nb_in + 2 * x + 1) * p1 + l) * 128;
            o  = ((n * p0 + x) * (2 * p1) + 2 * l + j) * 128;
        }
        sOff0[tid] = r0; sOff1[tid] = r1; sOutOff[tid] = o;
        const float* bg = bias ? (bias + ((stage >= 1 && stage <= 3) ? g * 128 : 0)) : nullptr;
        sBias[tid] = bg ? bg[tid] : 0.0f;
    }
    __syncthreads();

    const uint32_t dynU = smem_u32(dyn);
    const bool f32in  = (stage == 0);
    const int  nk     = K >> 5;                   // chunks of 32

    // ---- issue loads for chunk ch into buffer ch%3 ----
    auto issue_chunk = [&](int ch) {
        if (ch < nk) {
            const int bufo = (ch % NBUF) * BUF_BYTES;
            const int k0 = ch << 5;
            const bool hi_half = (k0 < 128);
            const int  kk = hi_half ? k0 : (k0 - 128);
            if (f32in) {
                // A from fp32 x: load + split + STS (stage 0 only)
                char* Ah = dyn + bufo; char* Al = dyn + bufo + TILE_B;
                #pragma unroll
                for (int i = 0; i < 4; i++) {
                    const int s = tid + (i << 8);
                    const int row = s >> 3, q = s & 7;
                    const int off = sOff0[row] + kk + (q << 2);
                    const float4 v = *(const float4*)(inF + off);
                    const __nv_bfloat16 hx = __float2bfloat16(v.x), hy = __float2bfloat16(v.y);
                    const __nv_bfloat16 hz = __float2bfloat16(v.z), hw = __float2bfloat16(v.w);
                    const __nv_bfloat16 lx = __float2bfloat16(v.x - __bfloat162float(hx));
                    const __nv_bfloat16 ly = __float2bfloat16(v.y - __bfloat162float(hy));
                    const __nv_bfloat16 lz = __float2bfloat16(v.z - __bfloat162float(hz));
                    const __nv_bfloat16 lw = __float2bfloat16(v.w - __bfloat162float(hw));
                    const unsigned sw = SW64((unsigned)(row * 64 + q * 8));
                    *(uint2*)(Ah + sw) = make_uint2(packbf(hx, hy), packbf(hz, hw));
                    *(uint2*)(Al + sw) = make_uint2(packbf(lx, ly), packbf(lz, lw));
                }
            } else {
                // A hi/lo via cp.async: 2 planes x 128 rows x 4 x 16B
                const uint32_t AhU = dynU + bufo, AlU = dynU + bufo + TILE_B;
                #pragma unroll
                for (int i = 0; i < 4; i++) {
                    const int s = tid + (i << 8);
                    const int plane = s >> 9, row = (s >> 2) & 127, u = s & 3;
                    const int off = (hi_half ? sOff0[row] : sOff1[row]) + kk + (u << 3);
                    const unsigned short* src = (plane ? inLo : inHi) + off;
                    const uint32_t dst = (plane ? AlU : AhU) + SW64((unsigned)(row * 64 + u * 16));
                    CP_ASYNC16(dst, src);
                }
            }
            // W hi/lo via cp.async: 2 planes x 128 n-rows x 4 x 16B
            {
                const uint32_t WhU = dynU + bufo + 2 * TILE_B, WlU = dynU + bufo + 3 * TILE_B;
                #pragma unroll
                for (int i = 0; i < 4; i++) {
                    const int s = tid + (i << 8);
                    const int plane = s >> 9, n = (s >> 2) & 127, u = s & 3;
                    const __nv_bfloat16* src = (plane ? wlg : whg) + (size_t)n * K + k0 + (u << 3);
                    const uint32_t dst = (plane ? WlU : WhU) + SW64((unsigned)(n * 64 + u * 16));
                    CP_ASYNC16(dst, src);
                }
            }
        }
        CP_COMMIT();
    };

    // ---- warp tiling: 4x2 warps, each m32 x n64 ----
    const int warpM = wid >> 1, warpN = wid & 1;
    int offA[2], swA[2];
    #pragma unroll
    for (int mt = 0; mt < 2; mt++) {
        const int r = warpM * 32 + mt * 16 + ((lane & 8) ? 8 : 0) + (lane & 7);
        offA[mt] = r * 64; swA[mt] = ((r >> 1) & 3) << 4;
    }
    const int kaddA = (lane & 16) ? 16 : 0;
    int offB[4], swB[4];
    #pragma unroll
    for (int nt2 = 0; nt2 < 4; nt2++) {
        const int n = warpN * 64 + nt2 * 16 + ((lane & 16) ? 8 : 0) + (lane & 7);
        offB[nt2] = n * 64; swB[nt2] = ((n >> 1) & 3) << 4;
    }
    const int kaddB = (lane & 8) ? 16 : 0;

    float c[2][8][4];
    #pragma unroll
    for (int mt = 0; mt < 2; mt++)
        #pragma unroll
        for (int nt = 0; nt < 8; nt++)
            #pragma unroll
            for (int i = 0; i < 4; i++) c[mt][nt][i] = 0.0f;

    // ---- pipelined mainloop (R9 ordering) + B-fragment ping-pong ----
    issue_chunk(0);
    issue_chunk(1);
    for (int ch = 0; ch < nk; ch++) {
        CP_WAIT1();                                // chunk ch's group retired
        __syncthreads();                           // data visible; prev-buf reads done

        const uint32_t bufU = dynU + (ch % NBUF) * BUF_BYTES;
        const uint32_t AhU = bufU, AlU = bufU + TILE_B;
        const uint32_t WhU = bufU + 2 * TILE_B, WlU = bufU + 3 * TILE_B;
        #pragma unroll
        for (int ks = 0; ks < 2; ks++) {
            const int kb = ks * 32;
            // A fragments for this ks (hi + lo)
            uint32_t ah[2][4], al[2][4];
            ldsm_x4(ah[0], AhU + offA[0] + ((kb + kaddA) ^ swA[0]));
            ldsm_x4(ah[1], AhU + offA[1] + ((kb + kaddA) ^ swA[1]));
            ldsm_x4(al[0], AlU + offA[0] + ((kb + kaddA) ^ swA[0]));
            ldsm_x4(al[1], AlU + offA[1] + ((kb + kaddA) ^ swA[1]));
            // B fragment ping-pong: load nt2+1 before MMAs of nt2
            uint32_t bh[2][4], bl[2][4];
            ldsm_x4(bh[0], WhU + offB[0] + ((kb + kaddB) ^ swB[0]));
            ldsm_x4(bl[0], WlU + offB[0] + ((kb + kaddB) ^ swB[0]));
            #pragma unroll
            for (int nt2 = 0; nt2 < 4; nt2++) {
                const int cur = nt2 & 1, nxt = cur ^ 1;
                if (nt2 < 3) {
                    ldsm_x4(bh[nxt], WhU + offB[nt2 + 1] + ((kb + kaddB) ^ swB[nt2 + 1]));
                    ldsm_x4(bl[nxt], WlU + offB[nt2 + 1] + ((kb + kaddB) ^ swB[nt2 + 1]));
                }
                float* c00 = c[0][nt2 * 2 + 0];
                float* c01 = c[0][nt2 * 2 + 1];
                float* c10 = c[1][nt2 * 2 + 0];
                float* c11 = c[1][nt2 * 2 + 1];
                // term Ah*Wh — 4 independent chains, round-robin
                mma_bf16(c00, ah[0], bh[cur] + 0); mma_bf16(c01, ah[0], bh[cur] + 2);
                mma_bf16(c10, ah[1], bh[cur] + 0); mma_bf16(c11, ah[1], bh[cur] + 2);
                // term Al*Wh
                mma_bf16(c00, al[0], bh[cur] + 0); mma_bf16(c01, al[0], bh[cur] + 2);
                mma_bf16(c10, al[1], bh[cur] + 0); mma_bf16(c11, al[1], bh[cur] + 2);
                // term Ah*Wl
                mma_bf16(c00, ah[0], bl[cur] + 0); mma_bf16(c01, ah[0], bl[cur] + 2);
                mma_bf16(c10, ah[1], bl[cur] + 0); mma_bf16(c11, ah[1], bl[cur] + 2);
            }
        }
        issue_chunk(ch + 2);                       // writes buf read at iter ch-1 (safe)
    }

    // ---- epilogue: bias + relu, scatter (hi/lo planes or fp32 final) ----
    const bool doRelu = (stage != 4);
    const bool f32out = (stage == 4);
    #pragma unroll
    for (int mt = 0; mt < 2; mt++) {
        const int rbase = warpM * 32 + mt * 16 + (lane >> 2);
        #pragma unroll
        for (int h = 0; h < 2; h++) {
            const int off = sOutOff[rbase + h * 8];
            #pragma unroll
            for (int nt = 0; nt < 8; nt++) {
                const int col = warpN * 64 + nt * 8 + 2 * (lane & 3);
                float v0 = c[mt][nt][h * 2 + 0] + sBias[col];
                float v1 = c[mt][nt][h * 2 + 1] + sBias[col + 1];
                if (doRelu) { v0 = fmaxf(v0, 0.0f); v1 = fmaxf(v1, 0.0f); }
                if (f32out) {
                    float2 v; v.x = v0; v.y = v1;
                    *(float2*)(outF + off + col) = v;
                } else {
                    const __nv_bfloat16 h0 = __float2bfloat16(v0);
                    const __nv_bfloat16 h1 = __float2bfloat16(v1);
                    const __nv_bfloat16 l0 = __float2bfloat16(v0 - __bfloat162float(h0));
                    const __nv_bfloat16 l1 = __float2bfloat16(v1 - __bfloat162float(h1));
                    *(unsigned*)(outHi + off + col) = packbf(h0, h1);
                    *(unsigned*)(outLo + off + col) = packbf(l0, l1);
                }
            }
        }
    }
}

// ---------------- launch ----------------
extern "C" void kernel_launch(void* const* d_in, const int* in_sizes, int n_in,
                              void* d_out, int out_size)
{
    (void)in_sizes; (void)n_in; (void)out_size;
    const float* x  = (const float*)d_in[0];
    const float* xf = (const float*)d_in[1];
    const float* xb = (const float*)d_in[2];
    const float* f1 = (const float*)d_in[3];
    const float* b1 = (const float*)d_in[4];
    const float* f2 = (const float*)d_in[5];
    const float* b2 = (const float*)d_in[6];
    const float* f3 = (const float*)d_in[7];
    const float* b3 = (const float*)d_in[8];
    const float* md = (const float*)d_in[9];
    const float* mb = (const float*)d_in[10];
    const float* f4 = (const float*)d_in[11];
    const float* b4 = (const float*)d_in[12];
    const float* f5 = (const float*)d_in[13];
    const float* b5 = (const float*)d_in[14];
    const float* f6 = (const float*)d_in[15];
    const float* b6 = (const float*)d_in[16];
    const float* kf = (const float*)d_in[17];
    float* out = (float*)d_out;

    unsigned short *hA, *lA, *hB, *lB, *whiR, *wloR;
    cudaGetSymbolAddress((void**)&hA, g_hiA);
    cudaGetSymbolAddress((void**)&lA, g_loA);
    cudaGetSymbolAddress((void**)&hB, g_hiB);
    cudaGetSymbolAddress((void**)&lB, g_loB);
    cudaGetSymbolAddress((void**)&whiR, g_whi_raw);
    cudaGetSymbolAddress((void**)&wloR, g_wlo_raw);
    const __nv_bfloat16* whi = (const __nv_bfloat16*)whiR;
    const __nv_bfloat16* wlo = (const __nv_bfloat16*)wloR;

    cudaFuncSetAttribute(stage_mma, cudaFuncAttributeMaxDynamicSharedMemorySize, DYN_SMEM);

    prep_weights<<<(WTOTAL + 255) / 256, 256>>>(xf, f1, f2, f3, md, f4, f5, f6, kf);

    const int Oxf = 0, Of1 = 16384, Of2 = 81920, Of3 = 212992, Omd = 475136,
              Of4 = 1523712, Of5 = 1785856, Of6 = 1916928, Okf = 1982464;

    const dim3 grid(512), block(256);
    // (inF, inHi, inLo, wh, wl, bias, outF, outHi, outLo, stage, p0, p1, tpg, K)
    stage_mma<<<grid, block, DYN_SMEM>>>(x, nullptr, nullptr, whi + Oxf, wlo + Oxf, xb,
                                         nullptr, hA, lA, 0, 0, 0, 512, 128);
    stage_mma<<<grid, block, DYN_SMEM>>>(nullptr, hA, lA, whi + Of1, wlo + Of1, b1,
                                         nullptr, hB, lB, 1, 2, 32, 256, 256);
    stage_mma<<<grid, block, DYN_SMEM>>>(nullptr, hB, lB, whi + Of2, wlo + Of2, b2,
                                         nullptr, hA, lA, 1, 4, 16, 128, 256);
    stage_mma<<<grid, block, DYN_SMEM>>>(nullptr, hA, lA, whi + Of3, wlo + Of3, b3,
                                         nullptr, hB, lB, 1, 8, 8, 64, 256);
    stage_mma<<<grid, block, DYN_SMEM>>>(nullptr, hB, lB, whi + Omd, wlo + Omd, mb,
                                         nullptr, hA, lA, 2, 0, 0, 8, 128);
    stage_mma<<<grid, block, DYN_SMEM>>>(nullptr, hA, lA, whi + Of4, wlo + Of4, b4,
                                         nullptr, hB, lB, 3, 4, 8, 64, 256);
    stage_mma<<<grid, block, DYN_SMEM>>>(nullptr, hB, lB, whi + Of5, wlo + Of5, b5,
                                         nullptr, hA, lA, 3, 2, 16, 128, 256);
    stage_mma<<<grid, block, DYN_SMEM>>>(nullptr, hA, lA, whi + Of6, wlo + Of6, b6,
                                         nullptr, hB, lB, 3, 1, 32, 256, 256);
    stage_mma<<<grid, block, DYN_SMEM>>>(nullptr, hB, lB, whi + Okf, wlo + Okf, nullptr,
                                         out, nullptr, nullptr, 4, 0, 0, 512, 128);
}

// round 14
// speedup vs baseline: 1.2316x; 1.0599x over previous
#include <cuda_runtime.h>
#include <cuda_bf16.h>
#include <cstdint>
#include <cstddef>

// ButterflyLayer1D: 9 chained batched GEMMs (M=65536, N=128, K in {128,256})
// via warp-level mma.sync bf16, split precision (hi+lo planes):
//   D = Ah*Wh + Al*Wh + Ah*Wl   (fp32 accum, residual ~2^-16)
// R13: CTA tile 64x128 (warp tile m16n64), 24KB buffers x3, 3 CTAs/SM for
// higher occupancy (latency-bound profile: all pipes <50%, occ 22%).

#define SW64(off) ((off) ^ (((off) >> 3) & 0x30))

__device__ __forceinline__ uint32_t smem_u32(const void* p) {
    uint32_t a;
    asm("{ .reg .u64 t; cvta.to.shared.u64 t, %1; cvt.u32.u64 %0, t; }" : "=r"(a) : "l"(p));
    return a;
}
__device__ __forceinline__ void ldsm_x4(uint32_t* r, uint32_t a) {
    asm volatile("ldmatrix.sync.aligned.m8n8.x4.shared.b16 {%0,%1,%2,%3}, [%4];"
        : "=r"(r[0]), "=r"(r[1]), "=r"(r[2]), "=r"(r[3]) : "r"(a));
}
__device__ __forceinline__ void mma_bf16(float* d, const uint32_t* a, const uint32_t* b) {
    asm volatile(
        "mma.sync.aligned.m16n8k16.row.col.f32.bf16.bf16.f32 "
        "{%0,%1,%2,%3}, {%4,%5,%6,%7}, {%8,%9}, {%0,%1,%2,%3};"
        : "+f"(d[0]), "+f"(d[1]), "+f"(d[2]), "+f"(d[3])
        : "r"(a[0]), "r"(a[1]), "r"(a[2]), "r"(a[3]), "r"(b[0]), "r"(b[1]));
}
__device__ __forceinline__ unsigned packbf(__nv_bfloat16 a, __nv_bfloat16 b) {
    return ((unsigned)__bfloat16_as_ushort(b) << 16) | (unsigned)__bfloat16_as_ushort(a);
}
#define CP_ASYNC16(dst, src) \
    asm volatile("cp.async.cg.shared.global [%0], [%1], 16;" :: "r"(dst), "l"(src))
#define CP_COMMIT() asm volatile("cp.async.commit_group;" ::: "memory")
#define CP_WAIT1()  asm volatile("cp.async.wait_group 1;" ::: "memory")

// ---------------- global scratch ----------------
#define ACT_ELEMS (1024 * 64 * 128)
__device__ unsigned short g_hiA[ACT_ELEMS];
__device__ unsigned short g_loA[ACT_ELEMS];
__device__ unsigned short g_hiB[ACT_ELEMS];
__device__ unsigned short g_loB[ACT_ELEMS];
#define WTOTAL 1998848
__device__ unsigned short g_whi_raw[WTOTAL];
__device__ unsigned short g_wlo_raw[WTOTAL];

// ---------------- weight prep: transpose + split to bf16 hi/lo ----------------
__global__ void prep_weights(const float* __restrict__ xf, const float* __restrict__ f1,
                             const float* __restrict__ f2, const float* __restrict__ f3,
                             const float* __restrict__ md, const float* __restrict__ f4,
                             const float* __restrict__ f5, const float* __restrict__ f6,
                             const float* __restrict__ kf)
{
    const int e = blockIdx.x * blockDim.x + threadIdx.x;
    if (e >= WTOTAL) return;
    const int off[10] = {0, 16384, 81920, 212992, 475136, 1523712, 1785856, 1916928, 1982464, WTOTAL};
    int t = 0;
    #pragma unroll
    for (int i = 1; i < 9; i++) if (e >= off[i]) t = i;
    const int K = (t == 0 || t == 4 || t == 8) ? 128 : 256;
    const float* src;
    switch (t) {
        case 0: src = xf; break; case 1: src = f1; break; case 2: src = f2; break;
        case 3: src = f3; break; case 4: src = md; break; case 5: src = f4; break;
        case 6: src = f5; break; case 7: src = f6; break; default: src = kf; break;
    }
    const int local = e - off[t];
    const int per = K * 128;
    const int g = local / per, rem = local % per;
    const int kk = rem >> 7, n = rem & 127;       // src [g][kk][n]
    const float v = src[local];
    const __nv_bfloat16 h = __float2bfloat16(v);
    const float lr = v - __bfloat162float(h);
    const int di = off[t] + g * per + n * K + kk; // dst [g][n][kk]
    g_whi_raw[di] = __bfloat16_as_ushort(h);
    g_wlo_raw[di] = __bfloat16_as_ushort(__float2bfloat16(lr));
}

// ---------------- stage kernel ----------------
// CTA tile 64x128, K chunks of 32, 3-buffer cp.async pipeline (depth 2).
// Per buffer: Ah/Al (64x64B = 4KB each) + Wh/Wl (128x64B = 8KB each) = 24KB.
#define TILE_A   4096
#define TILE_W   8192
#define BUF_BYTES 24576
#define NBUF 3
#define DYN_SMEM  (NBUF * BUF_BYTES)

__global__ __launch_bounds__(256, 3)
void stage_mma(const float* __restrict__ inF,
               const unsigned short* __restrict__ inHi, const unsigned short* __restrict__ inLo,
               const __nv_bfloat16* __restrict__ wh, const __nv_bfloat16* __restrict__ wl,
               const float* __restrict__ bias,
               float* __restrict__ outF, unsigned short* __restrict__ outHi,
               unsigned short* __restrict__ outLo,
               int stage, int p0, int p1, int tpg, int K)
{
    __shared__ int   sOff0[64];
    __shared__ int   sOff1[64];
    __shared__ int   sOutOff[64];
    __shared__ float sBias[128];
    extern __shared__ __align__(16) char dyn[];

    const int tid = threadIdx.x;
    const int lane = tid & 31, wid = tid >> 5;
    const int g    = blockIdx.x / tpg;
    const int tile = blockIdx.x % tpg;

    const size_t gstride = (size_t)K * 128;
    const __nv_bfloat16* whg = wh + (size_t)g * gstride;
    const __nv_bfloat16* wlg = wl + (size_t)g * gstride;

    // ---- per-row gather/scatter element offsets (proven indexing, 64 rows) ----
    if (tid < 64) {
        const int t = tile * 64 + tid;
        int r0 = 0, r1 = 0, o = 0;
        if (stage == 0 || stage == 4) {
            r0 = t * 128; r1 = r0;
            o  = t * 128;
        } else if (stage == 1) {                  // down
            const int n = t / p1, l = t % p1;
            int nb_in = p0 >> 1; if (nb_in == 0) nb_in = 1;
            r0 = ((n * nb_in + (g >> 1)) * (2 * p1) + 2 * l) * 128;
            r1 = r0 + 128;
            o  = ((n * p0 + g) * p1 + l) * 128;
        } else if (stage == 2) {                  // middle: g = k*8 + x
            const int n = t;
            const int k = g >> 3, x = g & 7;
            r0 = ((n * 8 + k) * 8 + x) * 128; r1 = r0;
            o  = ((n * 8 + x) * 8 + k) * 128;
        } else {                                  // up: g = 2x + j
            const int n = t / p1, l = t % p1;
            const int x = g >> 1, j = g & 1;
            const int nb_in = p0 * 2;
            r0 = ((n * nb_in + 2 * x)     * p1 + l) * 128;
            r1 = ((n * nb_in + 2 * x + 1) * p1 + l) * 128;
            o  = ((n * p0 + x) * (2 * p1) + 2 * l + j) * 128;
        }
        sOff0[tid] = r0; sOff1[tid] = r1; sOutOff[tid] = o;
    }
    if (tid < 128) {
        const float* bg = bias ? (bias + ((stage >= 1 && stage <= 3) ? g * 128 : 0)) : nullptr;
        sBias[tid] = bg ? bg[tid] : 0.0f;
    }
    __syncthreads();

    const uint32_t dynU = smem_u32(dyn);
    const bool f32in  = (stage == 0);
    const int  nk     = K >> 5;                   // chunks of 32

    // ---- issue loads for chunk ch into buffer ch%3 ----
    auto issue_chunk = [&](int ch) {
        if (ch < nk) {
            const int bufo = (ch % NBUF) * BUF_BYTES;
            const int k0 = ch << 5;
            const bool hi_half = (k0 < 128);
            const int  kk = hi_half ? k0 : (k0 - 128);
            if (f32in) {
                // A from fp32 x: 64 rows x 32k = 512 float4 slots (2 iters)
                char* Ah = dyn + bufo; char* Al = dyn + bufo + TILE_A;
                #pragma unroll
                for (int i = 0; i < 2; i++) {
                    const int s = tid + (i << 8);
                    const int row = s >> 3, q = s & 7;
                    const int off = sOff0[row] + kk + (q << 2);
                    const float4 v = *(const float4*)(inF + off);
                    const __nv_bfloat16 hx = __float2bfloat16(v.x), hy = __float2bfloat16(v.y);
                    const __nv_bfloat16 hz = __float2bfloat16(v.z), hw = __float2bfloat16(v.w);
                    const __nv_bfloat16 lx = __float2bfloat16(v.x - __bfloat162float(hx));
                    const __nv_bfloat16 ly = __float2bfloat16(v.y - __bfloat162float(hy));
                    const __nv_bfloat16 lz = __float2bfloat16(v.z - __bfloat162float(hz));
                    const __nv_bfloat16 lw = __float2bfloat16(v.w - __bfloat162float(hw));
                    const unsigned sw = SW64((unsigned)(row * 64 + q * 8));
                    *(uint2*)(Ah + sw) = make_uint2(packbf(hx, hy), packbf(hz, hw));
                    *(uint2*)(Al + sw) = make_uint2(packbf(lx, ly), packbf(lz, lw));
                }
            } else {
                // A hi/lo via cp.async: 2 planes x 64 rows x 4 x 16B = 512 slots
                const uint32_t AhU = dynU + bufo, AlU = dynU + bufo + TILE_A;
                #pragma unroll
                for (int i = 0; i < 2; i++) {
                    const int s = tid + (i << 8);
                    const int plane = s >> 8, row = (s >> 2) & 63, u = s & 3;
                    const int off = (hi_half ? sOff0[row] : sOff1[row]) + kk + (u << 3);
                    const unsigned short* src = (plane ? inLo : inHi) + off;
                    const uint32_t dst = (plane ? AlU : AhU) + SW64((unsigned)(row * 64 + u * 16));
                    CP_ASYNC16(dst, src);
                }
            }
            // W hi/lo via cp.async: 2 planes x 128 n-rows x 4 x 16B = 1024 slots
            {
                const uint32_t WhU = dynU + bufo + 2 * TILE_A;
                const uint32_t WlU = WhU + TILE_W;
                #pragma unroll
                for (int i = 0; i < 4; i++) {
                    const int s = tid + (i << 8);
                    const int plane = s >> 9, n = (s >> 2) & 127, u = s & 3;
                    const __nv_bfloat16* src = (plane ? wlg : whg) + (size_t)n * K + k0 + (u << 3);
                    const uint32_t dst = (plane ? WlU : WhU) + SW64((unsigned)(n * 64 + u * 16));
                    CP_ASYNC16(dst, src);
                }
            }
        }
        CP_COMMIT();
    };

    // ---- warp tiling: 4x2 warps, each m16 x n64 ----
    const int warpM = wid >> 1, warpN = wid & 1;
    const int rA = warpM * 16 + ((lane & 8) ? 8 : 0) + (lane & 7);
    const int offA = rA * 64, swA = ((rA >> 1) & 3) << 4;
    const int kaddA = (lane & 16) ? 16 : 0;
    int offB[4], swB[4];
    #pragma unroll
    for (int nt2 = 0; nt2 < 4; nt2++) {
        const int n = warpN * 64 + nt2 * 16 + ((lane & 16) ? 8 : 0) + (lane & 7);
        offB[nt2] = n * 64; swB[nt2] = ((n >> 1) & 3) << 4;
    }
    const int kaddB = (lane & 8) ? 16 : 0;

    float c[8][4];
    #pragma unroll
    for (int nt = 0; nt < 8; nt++)
        #pragma unroll
        for (int i = 0; i < 4; i++) c[nt][i] = 0.0f;

    // ---- pipelined mainloop + B-fragment ping-pong ----
    issue_chunk(0);
    issue_chunk(1);
    for (int ch = 0; ch < nk; ch++) {
        CP_WAIT1();                                // chunk ch's group retired
        __syncthreads();                           // data visible; prev-buf reads done

        const uint32_t bufU = dynU + (ch % NBUF) * BUF_BYTES;
        const uint32_t AhU = bufU, AlU = bufU + TILE_A;
        const uint32_t WhU = bufU + 2 * TILE_A, WlU = WhU + TILE_W;
        #pragma unroll
        for (int ks = 0; ks < 2; ks++) {
            const int kb = ks * 32;
            uint32_t ah[4], al[4];
            ldsm_x4(ah, AhU + offA + ((kb + kaddA) ^ swA));
            ldsm_x4(al, AlU + offA + ((kb + kaddA) ^ swA));
            // B fragment ping-pong: load nt2+1 before MMAs of nt2
            uint32_t bh[2][4], bl[2][4];
            ldsm_x4(bh[0], WhU + offB[0] + ((kb + kaddB) ^ swB[0]));
            ldsm_x4(bl[0], WlU + offB[0] + ((kb + kaddB) ^ swB[0]));
            #pragma unroll
            for (int nt2 = 0; nt2 < 4; nt2++) {
                const int cur = nt2 & 1, nxt = cur ^ 1;
                if (nt2 < 3) {
                    ldsm_x4(bh[nxt], WhU + offB[nt2 + 1] + ((kb + kaddB) ^ swB[nt2 + 1]));
                    ldsm_x4(bl[nxt], WlU + offB[nt2 + 1] + ((kb + kaddB) ^ swB[nt2 + 1]));
                }
                float* c0 = c[nt2 * 2 + 0];
                float* c1 = c[nt2 * 2 + 1];
                // term Ah*Wh
                mma_bf16(c0, ah, bh[cur] + 0); mma_bf16(c1, ah, bh[cur] + 2);
                // term Al*Wh
                mma_bf16(c0, al, bh[cur] + 0); mma_bf16(c1, al, bh[cur] + 2);
                // term Ah*Wl
                mma_bf16(c0, ah, bl[cur] + 0); mma_bf16(c1, ah, bl[cur] + 2);
            }
        }
        issue_chunk(ch + 2);                       // writes buf read at iter ch-1 (safe)
    }

    // ---- epilogue: bias + relu, scatter (hi/lo planes or fp32 final) ----
    const bool doRelu = (stage != 4);
    const bool f32out = (stage == 4);
    const int rbase = warpM * 16 + (lane >> 2);
    #pragma unroll
    for (int h = 0; h < 2; h++) {
        const int off = sOutOff[rbase + h * 8];
        #pragma unroll
        for (int nt = 0; nt < 8; nt++) {
            const int col = warpN * 64 + nt * 8 + 2 * (lane & 3);
            float v0 = c[nt][h * 2 + 0] + sBias[col];
            float v1 = c[nt][h * 2 + 1] + sBias[col + 1];
            if (doRelu) { v0 = fmaxf(v0, 0.0f); v1 = fmaxf(v1, 0.0f); }
            if (f32out) {
                float2 v; v.x = v0; v.y = v1;
                *(float2*)(outF + off + col) = v;
            } else {
                const __nv_bfloat16 h0 = __float2bfloat16(v0);
                const __nv_bfloat16 h1 = __float2bfloat16(v1);
                const __nv_bfloat16 l0 = __float2bfloat16(v0 - __bfloat162float(h0));
                const __nv_bfloat16 l1 = __float2bfloat16(v1 - __bfloat162float(h1));
                *(unsigned*)(outHi + off + col) = packbf(h0, h1);
                *(unsigned*)(outLo + off + col) = packbf(l0, l1);
            }
        }
    }
}

// ---------------- launch ----------------
extern "C" void kernel_launch(void* const* d_in, const int* in_sizes, int n_in,
                              void* d_out, int out_size)
{
    (void)in_sizes; (void)n_in; (void)out_size;
    const float* x  = (const float*)d_in[0];
    const float* xf = (const float*)d_in[1];
    const float* xb = (const float*)d_in[2];
    const float* f1 = (const float*)d_in[3];
    const float* b1 = (const float*)d_in[4];
    const float* f2 = (const float*)d_in[5];
    const float* b2 = (const float*)d_in[6];
    const float* f3 = (const float*)d_in[7];
    const float* b3 = (const float*)d_in[8];
    const float* md = (const float*)d_in[9];
    const float* mb = (const float*)d_in[10];
    const float* f4 = (const float*)d_in[11];
    const float* b4 = (const float*)d_in[12];
    const float* f5 = (const float*)d_in[13];
    const float* b5 = (const float*)d_in[14];
    const float* f6 = (const float*)d_in[15];
    const float* b6 = (const float*)d_in[16];
    const float* kf = (const float*)d_in[17];
    float* out = (float*)d_out;

    unsigned short *hA, *lA, *hB, *lB, *whiR, *wloR;
    cudaGetSymbolAddress((void**)&hA, g_hiA);
    cudaGetSymbolAddress((void**)&lA, g_loA);
    cudaGetSymbolAddress((void**)&hB, g_hiB);
    cudaGetSymbolAddress((void**)&lB, g_loB);
    cudaGetSymbolAddress((void**)&whiR, g_whi_raw);
    cudaGetSymbolAddress((void**)&wloR, g_wlo_raw);
    const __nv_bfloat16* whi = (const __nv_bfloat16*)whiR;
    const __nv_bfloat16* wlo = (const __nv_bfloat16*)wloR;

    cudaFuncSetAttribute(stage_mma, cudaFuncAttributeMaxDynamicSharedMemorySize, DYN_SMEM);

    prep_weights<<<(WTOTAL + 255) / 256, 256>>>(xf, f1, f2, f3, md, f4, f5, f6, kf);

    const int Oxf = 0, Of1 = 16384, Of2 = 81920, Of3 = 212992, Omd = 475136,
              Of4 = 1523712, Of5 = 1785856, Of6 = 1916928, Okf = 1982464;

    const dim3 grid(1024), block(256);
    // (inF, inHi, inLo, wh, wl, bias, outF, outHi, outLo, stage, p0, p1, tpg, K)
    stage_mma<<<grid, block, DYN_SMEM>>>(x, nullptr, nullptr, whi + Oxf, wlo + Oxf, xb,
                                         nullptr, hA, lA, 0, 0, 0, 1024, 128);
    stage_mma<<<grid, block, DYN_SMEM>>>(nullptr, hA, lA, whi + Of1, wlo + Of1, b1,
                                         nullptr, hB, lB, 1, 2, 32, 512, 256);
    stage_mma<<<grid, block, DYN_SMEM>>>(nullptr, hB, lB, whi + Of2, wlo + Of2, b2,
                                         nullptr, hA, lA, 1, 4, 16, 256, 256);
    stage_mma<<<grid, block, DYN_SMEM>>>(nullptr, hA, lA, whi + Of3, wlo + Of3, b3,
                                         nullptr, hB, lB, 1, 8, 8, 128, 256);
    stage_mma<<<grid, block, DYN_SMEM>>>(nullptr, hB, lB, whi + Omd, wlo + Omd, mb,
                                         nullptr, hA, lA, 2, 0, 0, 16, 128);
    stage_mma<<<grid, block, DYN_SMEM>>>(nullptr, hA, lA, whi + Of4, wlo + Of4, b4,
                                         nullptr, hB, lB, 3, 4, 8, 128, 256);
    stage_mma<<<grid, block, DYN_SMEM>>>(nullptr, hB, lB, whi + Of5, wlo + Of5, b5,
                                         nullptr, hA, lA, 3, 2, 16, 256, 256);
    stage_mma<<<grid, block, DYN_SMEM>>>(nullptr, hA, lA, whi + Of6, wlo + Of6, b6,
                                         nullptr, hB, lB, 3, 1, 32, 512, 256);
    stage_mma<<<grid, block, DYN_SMEM>>>(nullptr, hB, lB, whi + Okf, wlo + Okf, nullptr,
                                         out, nullptr, nullptr, 4, 0, 0, 1024, 128);
}

// round 15
// speedup vs baseline: 1.2918x; 1.0489x over previous
#include <cuda_runtime.h>
#include <cuda_bf16.h>
#include <cstdint>
#include <cstddef>

// ButterflyLayer1D: 9 chained batched GEMMs (M=65536, N=128, K in {128,256})
// via warp-level mma.sync bf16, split precision (hi+lo planes):
//   D = Ah*Wh + Al*Wh + Ah*Wl   (fp32 accum, residual ~2^-16)
// R15: CTA 64x128, block 128 (4 warps m32n64 -> 128B smem read per MMA),
// 4 CTAs/SM, NBUF=2 double buffer with two syncs per chunk.

#define SW64(off) ((off) ^ (((off) >> 3) & 0x30))

__device__ __forceinline__ uint32_t smem_u32(const void* p) {
    uint32_t a;
    asm("{ .reg .u64 t; cvta.to.shared.u64 t, %1; cvt.u32.u64 %0, t; }" : "=r"(a) : "l"(p));
    return a;
}
__device__ __forceinline__ void ldsm_x4(uint32_t* r, uint32_t a) {
    asm volatile("ldmatrix.sync.aligned.m8n8.x4.shared.b16 {%0,%1,%2,%3}, [%4];"
        : "=r"(r[0]), "=r"(r[1]), "=r"(r[2]), "=r"(r[3]) : "r"(a));
}
__device__ __forceinline__ void mma_bf16(float* d, const uint32_t* a, const uint32_t* b) {
    asm volatile(
        "mma.sync.aligned.m16n8k16.row.col.f32.bf16.bf16.f32 "
        "{%0,%1,%2,%3}, {%4,%5,%6,%7}, {%8,%9}, {%0,%1,%2,%3};"
        : "+f"(d[0]), "+f"(d[1]), "+f"(d[2]), "+f"(d[3])
        : "r"(a[0]), "r"(a[1]), "r"(a[2]), "r"(a[3]), "r"(b[0]), "r"(b[1]));
}
__device__ __forceinline__ unsigned packbf(__nv_bfloat16 a, __nv_bfloat16 b) {
    return ((unsigned)__bfloat16_as_ushort(b) << 16) | (unsigned)__bfloat16_as_ushort(a);
}
#define CP_ASYNC16(dst, src) \
    asm volatile("cp.async.cg.shared.global [%0], [%1], 16;" :: "r"(dst), "l"(src))
#define CP_COMMIT() asm volatile("cp.async.commit_group;" ::: "memory")
#define CP_WAIT1()  asm volatile("cp.async.wait_group 1;" ::: "memory")

// ---------------- global scratch ----------------
#define ACT_ELEMS (1024 * 64 * 128)
__device__ unsigned short g_hiA[ACT_ELEMS];
__device__ unsigned short g_loA[ACT_ELEMS];
__device__ unsigned short g_hiB[ACT_ELEMS];
__device__ unsigned short g_loB[ACT_ELEMS];
#define WTOTAL 1998848
__device__ unsigned short g_whi_raw[WTOTAL];
__device__ unsigned short g_wlo_raw[WTOTAL];

// ---------------- weight prep: transpose + split to bf16 hi/lo ----------------
__global__ void prep_weights(const float* __restrict__ xf, const float* __restrict__ f1,
                             const float* __restrict__ f2, const float* __restrict__ f3,
                             const float* __restrict__ md, const float* __restrict__ f4,
                             const float* __restrict__ f5, const float* __restrict__ f6,
                             const float* __restrict__ kf)
{
    const int e = blockIdx.x * blockDim.x + threadIdx.x;
    if (e >= WTOTAL) return;
    const int off[10] = {0, 16384, 81920, 212992, 475136, 1523712, 1785856, 1916928, 1982464, WTOTAL};
    int t = 0;
    #pragma unroll
    for (int i = 1; i < 9; i++) if (e >= off[i]) t = i;
    const int K = (t == 0 || t == 4 || t == 8) ? 128 : 256;
    const float* src;
    switch (t) {
        case 0: src = xf; break; case 1: src = f1; break; case 2: src = f2; break;
        case 3: src = f3; break; case 4: src = md; break; case 5: src = f4; break;
        case 6: src = f5; break; case 7: src = f6; break; default: src = kf; break;
    }
    const int local = e - off[t];
    const int per = K * 128;
    const int g = local / per, rem = local % per;
    const int kk = rem >> 7, n = rem & 127;       // src [g][kk][n]
    const float v = src[local];
    const __nv_bfloat16 h = __float2bfloat16(v);
    const float lr = v - __bfloat162float(h);
    const int di = off[t] + g * per + n * K + kk; // dst [g][n][kk]
    g_whi_raw[di] = __bfloat16_as_ushort(h);
    g_wlo_raw[di] = __bfloat16_as_ushort(__float2bfloat16(lr));
}

// ---------------- stage kernel ----------------
// CTA tile 64x128, K chunks of 32, NBUF=2 cp.async double buffer.
// Per buffer: Ah/Al (64x64B = 4KB each) + Wh/Wl (128x64B = 8KB each) = 24KB.
#define TILE_A   4096
#define TILE_W   8192
#define BUF_BYTES 24576
#define NBUF 2
#define DYN_SMEM  (NBUF * BUF_BYTES)

__global__ __launch_bounds__(128, 4)
void stage_mma(const float* __restrict__ inF,
               const unsigned short* __restrict__ inHi, const unsigned short* __restrict__ inLo,
               const __nv_bfloat16* __restrict__ wh, const __nv_bfloat16* __restrict__ wl,
               const float* __restrict__ bias,
               float* __restrict__ outF, unsigned short* __restrict__ outHi,
               unsigned short* __restrict__ outLo,
               int stage, int p0, int p1, int tpg, int K)
{
    __shared__ int   sOff0[64];
    __shared__ int   sOff1[64];
    __shared__ int   sOutOff[64];
    __shared__ float sBias[128];
    extern __shared__ __align__(16) char dyn[];

    const int tid = threadIdx.x;
    const int lane = tid & 31, wid = tid >> 5;
    const int g    = blockIdx.x / tpg;
    const int tile = blockIdx.x % tpg;

    const size_t gstride = (size_t)K * 128;
    const __nv_bfloat16* whg = wh + (size_t)g * gstride;
    const __nv_bfloat16* wlg = wl + (size_t)g * gstride;

    // ---- per-row gather/scatter element offsets (proven indexing, 64 rows) ----
    if (tid < 64) {
        const int t = tile * 64 + tid;
        int r0 = 0, r1 = 0, o = 0;
        if (stage == 0 || stage == 4) {
            r0 = t * 128; r1 = r0;
            o  = t * 128;
        } else if (stage == 1) {                  // down
            const int n = t / p1, l = t % p1;
            int nb_in = p0 >> 1; if (nb_in == 0) nb_in = 1;
            r0 = ((n * nb_in + (g >> 1)) * (2 * p1) + 2 * l) * 128;
            r1 = r0 + 128;
            o  = ((n * p0 + g) * p1 + l) * 128;
        } else if (stage == 2) {                  // middle: g = k*8 + x
            const int n = t;
            const int k = g >> 3, x = g & 7;
            r0 = ((n * 8 + k) * 8 + x) * 128; r1 = r0;
            o  = ((n * 8 + x) * 8 + k) * 128;
        } else {                                  // up: g = 2x + j
            const int n = t / p1, l = t % p1;
            const int x = g >> 1, j = g & 1;
            const int nb_in = p0 * 2;
            r0 = ((n * nb_in + 2 * x)     * p1 + l) * 128;
            r1 = ((n * nb_in + 2 * x + 1) * p1 + l) * 128;
            o  = ((n * p0 + x) * (2 * p1) + 2 * l + j) * 128;
        }
        sOff0[tid] = r0; sOff1[tid] = r1; sOutOff[tid] = o;
    }
    {
        const float* bg = bias ? (bias + ((stage >= 1 && stage <= 3) ? g * 128 : 0)) : nullptr;
        sBias[tid]       = bg ? bg[tid] : 0.0f;
        sBias[tid + 64]  = bg ? bg[tid + 64] : 0.0f;
    }
    __syncthreads();

    const uint32_t dynU = smem_u32(dyn);
    const bool f32in  = (stage == 0);
    const int  nk     = K >> 5;                   // chunks of 32

    // ---- issue loads for chunk ch into buffer ch%2 ----
    auto issue_chunk = [&](int ch) {
        if (ch < nk) {
            const int bufo = (ch % NBUF) * BUF_BYTES;
            const int k0 = ch << 5;
            const bool hi_half = (k0 < 128);
            const int  kk = hi_half ? k0 : (k0 - 128);
            if (f32in) {
                // A from fp32 x: 64 rows x 32k = 512 float4 slots (4 iters @128thr)
                char* Ah = dyn + bufo; char* Al = dyn + bufo + TILE_A;
                #pragma unroll
                for (int i = 0; i < 4; i++) {
                    const int s = tid + (i << 7);
                    const int row = s >> 3, q = s & 7;
                    const int off = sOff0[row] + kk + (q << 2);
                    const float4 v = *(const float4*)(inF + off);
                    const __nv_bfloat16 hx = __float2bfloat16(v.x), hy = __float2bfloat16(v.y);
                    const __nv_bfloat16 hz = __float2bfloat16(v.z), hw = __float2bfloat16(v.w);
                    const __nv_bfloat16 lx = __float2bfloat16(v.x - __bfloat162float(hx));
                    const __nv_bfloat16 ly = __float2bfloat16(v.y - __bfloat162float(hy));
                    const __nv_bfloat16 lz = __float2bfloat16(v.z - __bfloat162float(hz));
                    const __nv_bfloat16 lw = __float2bfloat16(v.w - __bfloat162float(hw));
                    const unsigned sw = SW64((unsigned)(row * 64 + q * 8));
                    *(uint2*)(Ah + sw) = make_uint2(packbf(hx, hy), packbf(hz, hw));
                    *(uint2*)(Al + sw) = make_uint2(packbf(lx, ly), packbf(lz, lw));
                }
            } else {
                // A hi/lo via cp.async: 2 planes x 64 rows x 4 x 16B = 512 slots
                const uint32_t AhU = dynU + bufo, AlU = dynU + bufo + TILE_A;
                #pragma unroll
                for (int i = 0; i < 4; i++) {
                    const int s = tid + (i << 7);
                    const int plane = s >> 8, row = (s >> 2) & 63, u = s & 3;
                    const int off = (hi_half ? sOff0[row] : sOff1[row]) + kk + (u << 3);
                    const unsigned short* src = (plane ? inLo : inHi) + off;
                    const uint32_t dst = (plane ? AlU : AhU) + SW64((unsigned)(row * 64 + u * 16));
                    CP_ASYNC16(dst, src);
                }
            }
            // W hi/lo via cp.async: 2 planes x 128 n-rows x 4 x 16B = 1024 slots
            {
                const uint32_t WhU = dynU + bufo + 2 * TILE_A;
                const uint32_t WlU = WhU + TILE_W;
                #pragma unroll
                for (int i = 0; i < 8; i++) {
                    const int s = tid + (i << 7);
                    const int plane = s >> 9, n = (s >> 2) & 127, u = s & 3;
                    const __nv_bfloat16* src = (plane ? wlg : whg) + (size_t)n * K + k0 + (u << 3);
                    const uint32_t dst = (plane ? WlU : WhU) + SW64((unsigned)(n * 64 + u * 16));
                    CP_ASYNC16(dst, src);
                }
            }
        }
        CP_COMMIT();
    };

    // ---- warp tiling: 2x2 warps, each m32 x n64 ----
    const int warpM = wid >> 1, warpN = wid & 1;
    int offA[2], swA[2];
    #pragma unroll
    for (int mt = 0; mt < 2; mt++) {
        const int r = warpM * 32 + mt * 16 + ((lane & 8) ? 8 : 0) + (lane & 7);
        offA[mt] = r * 64; swA[mt] = ((r >> 1) & 3) << 4;
    }
    const int kaddA = (lane & 16) ? 16 : 0;
    int offB[4], swB[4];
    #pragma unroll
    for (int nt2 = 0; nt2 < 4; nt2++) {
        const int n = warpN * 64 + nt2 * 16 + ((lane & 16) ? 8 : 0) + (lane & 7);
        offB[nt2] = n * 64; swB[nt2] = ((n >> 1) & 3) << 4;
    }
    const int kaddB = (lane & 8) ? 16 : 0;

    float c[2][8][4];
    #pragma unroll
    for (int mt = 0; mt < 2; mt++)
        #pragma unroll
        for (int nt = 0; nt < 8; nt++)
            #pragma unroll
            for (int i = 0; i < 4; i++) c[mt][nt][i] = 0.0f;

    // ---- double-buffered mainloop, two syncs per chunk ----
    issue_chunk(0);
    issue_chunk(1);
    for (int ch = 0; ch < nk; ch++) {
        CP_WAIT1();                                // chunk ch's group retired
        __syncthreads();                           // data visible to all warps

        const uint32_t bufU = dynU + (ch % NBUF) * BUF_BYTES;
        const uint32_t AhU = bufU, AlU = bufU + TILE_A;
        const uint32_t WhU = bufU + 2 * TILE_A, WlU = WhU + TILE_W;
        #pragma unroll
        for (int ks = 0; ks < 2; ks++) {
            const int kb = ks * 32;
            uint32_t ah[2][4], al[2][4];
            ldsm_x4(ah[0], AhU + offA[0] + ((kb + kaddA) ^ swA[0]));
            ldsm_x4(ah[1], AhU + offA[1] + ((kb + kaddA) ^ swA[1]));
            ldsm_x4(al[0], AlU + offA[0] + ((kb + kaddA) ^ swA[0]));
            ldsm_x4(al[1], AlU + offA[1] + ((kb + kaddA) ^ swA[1]));
            // B fragment ping-pong: load nt2+1 before MMAs of nt2
            uint32_t bh[2][4], bl[2][4];
            ldsm_x4(bh[0], WhU + offB[0] + ((kb + kaddB) ^ swB[0]));
            ldsm_x4(bl[0], WlU + offB[0] + ((kb + kaddB) ^ swB[0]));
            #pragma unroll
            for (int nt2 = 0; nt2 < 4; nt2++) {
                const int cur = nt2 & 1, nxt = cur ^ 1;
                if (nt2 < 3) {
                    ldsm_x4(bh[nxt], WhU + offB[nt2 + 1] + ((kb + kaddB) ^ swB[nt2 + 1]));
                    ldsm_x4(bl[nxt], WlU + offB[nt2 + 1] + ((kb + kaddB) ^ swB[nt2 + 1]));
                }
                float* c00 = c[0][nt2 * 2 + 0];
                float* c01 = c[0][nt2 * 2 + 1];
                float* c10 = c[1][nt2 * 2 + 0];
                float* c11 = c[1][nt2 * 2 + 1];
                // term Ah*Wh — 4 independent chains, round-robin
                mma_bf16(c00, ah[0], bh[cur] + 0); mma_bf16(c01, ah[0], bh[cur] + 2);
                mma_bf16(c10, ah[1], bh[cur] + 0); mma_bf16(c11, ah[1], bh[cur] + 2);
                // term Al*Wh
                mma_bf16(c00, al[0], bh[cur] + 0); mma_bf16(c01, al[0], bh[cur] + 2);
                mma_bf16(c10, al[1], bh[cur] + 0); mma_bf16(c11, al[1], bh[cur] + 2);
                // term Ah*Wl
                mma_bf16(c00, ah[0], bl[cur] + 0); mma_bf16(c01, ah[0], bl[cur] + 2);
                mma_bf16(c10, ah[1], bl[cur] + 0); mma_bf16(c11, ah[1], bl[cur] + 2);
            }
        }
        __syncthreads();                           // all warps done reading buf ch%2
        issue_chunk(ch + 2);                       // safe to overwrite it now
    }

    // ---- epilogue: bias + relu, scatter (hi/lo planes or fp32 final) ----
    const bool doRelu = (stage != 4);
    const bool f32out = (stage == 4);
    #pragma unroll
    for (int mt = 0; mt < 2; mt++) {
        const int rbase = warpM * 32 + mt * 16 + (lane >> 2);
        #pragma unroll
        for (int h = 0; h < 2; h++) {
            const int off = sOutOff[rbase + h * 8];
            #pragma unroll
            for (int nt = 0; nt < 8; nt++) {
                const int col = warpN * 64 + nt * 8 + 2 * (lane & 3);
                float v0 = c[mt][nt][h * 2 + 0] + sBias[col];
                float v1 = c[mt][nt][h * 2 + 1] + sBias[col + 1];
                if (doRelu) { v0 = fmaxf(v0, 0.0f); v1 = fmaxf(v1, 0.0f); }
                if (f32out) {
                    float2 v; v.x = v0; v.y = v1;
                    *(float2*)(outF + off + col) = v;
                } else {
                    const __nv_bfloat16 h0 = __float2bfloat16(v0);
                    const __nv_bfloat16 h1 = __float2bfloat16(v1);
                    const __nv_bfloat16 l0 = __float2bfloat16(v0 - __bfloat162float(h0));
                    const __nv_bfloat16 l1 = __float2bfloat16(v1 - __bfloat162float(h1));
                    *(unsigned*)(outHi + off + col) = packbf(h0, h1);
                    *(unsigned*)(outLo + off + col) = packbf(l0, l1);
                }
            }
        }
    }
}

// ---------------- launch ----------------
extern "C" void kernel_launch(void* const* d_in, const int* in_sizes, int n_in,
                              void* d_out, int out_size)
{
    (void)in_sizes; (void)n_in; (void)out_size;
    const float* x  = (const float*)d_in[0];
    const float* xf = (const float*)d_in[1];
    const float* xb = (const float*)d_in[2];
    const float* f1 = (const float*)d_in[3];
    const float* b1 = (const float*)d_in[4];
    const float* f2 = (const float*)d_in[5];
    const float* b2 = (const float*)d_in[6];
    const float* f3 = (const float*)d_in[7];
    const float* b3 = (const float*)d_in[8];
    const float* md = (const float*)d_in[9];
    const float* mb = (const float*)d_in[10];
    const float* f4 = (const float*)d_in[11];
    const float* b4 = (const float*)d_in[12];
    const float* f5 = (const float*)d_in[13];
    const float* b5 = (const float*)d_in[14];
    const float* f6 = (const float*)d_in[15];
    const float* b6 = (const float*)d_in[16];
    const float* kf = (const float*)d_in[17];
    float* out = (float*)d_out;

    unsigned short *hA, *lA, *hB, *lB, *whiR, *wloR;
    cudaGetSymbolAddress((void**)&hA, g_hiA);
    cudaGetSymbolAddress((void**)&lA, g_loA);
    cudaGetSymbolAddress((void**)&hB, g_hiB);
    cudaGetSymbolAddress((void**)&lB, g_loB);
    cudaGetSymbolAddress((void**)&whiR, g_whi_raw);
    cudaGetSymbolAddress((void**)&wloR, g_wlo_raw);
    const __nv_bfloat16* whi = (const __nv_bfloat16*)whiR;
    const __nv_bfloat16* wlo = (const __nv_bfloat16*)wloR;

    cudaFuncSetAttribute(stage_mma, cudaFuncAttributeMaxDynamicSharedMemorySize, DYN_SMEM);

    prep_weights<<<(WTOTAL + 255) / 256, 256>>>(xf, f1, f2, f3, md, f4, f5, f6, kf);

    const int Oxf = 0, Of1 = 16384, Of2 = 81920, Of3 = 212992, Omd = 475136,
              Of4 = 1523712, Of5 = 1785856, Of6 = 1916928, Okf = 1982464;

    const dim3 grid(1024), block(128);
    // (inF, inHi, inLo, wh, wl, bias, outF, outHi, outLo, stage, p0, p1, tpg, K)
    stage_mma<<<grid, block, DYN_SMEM>>>(x, nullptr, nullptr, whi + Oxf, wlo + Oxf, xb,
                                         nullptr, hA, lA, 0, 0, 0, 1024, 128);
    stage_mma<<<grid, block, DYN_SMEM>>>(nullptr, hA, lA, whi + Of1, wlo + Of1, b1,
                                         nullptr, hB, lB, 1, 2, 32, 512, 256);
    stage_mma<<<grid, block, DYN_SMEM>>>(nullptr, hB, lB, whi + Of2, wlo + Of2, b2,
                                         nullptr, hA, lA, 1, 4, 16, 256, 256);
    stage_mma<<<grid, block, DYN_SMEM>>>(nullptr, hA, lA, whi + Of3, wlo + Of3, b3,
                                         nullptr, hB, lB, 1, 8, 8, 128, 256);
    stage_mma<<<grid, block, DYN_SMEM>>>(nullptr, hB, lB, whi + Omd, wlo + Omd, mb,
                                         nullptr, hA, lA, 2, 0, 0, 16, 128);
    stage_mma<<<grid, block, DYN_SMEM>>>(nullptr, hA, lA, whi + Of4, wlo + Of4, b4,
                                         nullptr, hB, lB, 3, 4, 8, 128, 256);
    stage_mma<<<grid, block, DYN_SMEM>>>(nullptr, hB, lB, whi + Of5, wlo + Of5, b5,
                                         nullptr, hA, lA, 3, 2, 16, 256, 256);
    stage_mma<<<grid, block, DYN_SMEM>>>(nullptr, hA, lA, whi + Of6, wlo + Of6, b6,
                                         nullptr, hB, lB, 3, 1, 32, 512, 256);
    stage_mma<<<grid, block, DYN_SMEM>>>(nullptr, hB, lB, whi + Okf, wlo + Okf, nullptr,
                                         out, nullptr, nullptr, 4, 0, 0, 1024, 128);
}

// round 16
// speedup vs baseline: 1.6847x; 1.3041x over previous
#include <cuda_runtime.h>
#include <cuda_fp16.h>
#include <cstdint>
#include <cstddef>

// ButterflyLayer1D: 9 chained batched GEMMs (M=65536, N=128, K in {128,256})
// via warp-level mma.sync fp16, 2-term split precision:
//   activations A = Ah + Al (both fp16, representation err ~2^-24)
//   weights W stored as single fp16 plane (err ~2^-12)
//   D = Ah*W + Al*W  (fp32 accum) -> per-layer error ~2^-12, measured metric
//   tracks single-layer scale (bf16 runs: 1.3e-5 ~= 2^-16) -> expect ~2.4e-4.
// R16: 2 MMAs per k16 instead of 3 (legacy HMMA cap ~50% reached; only lever
// left is fewer MMAs). CTA 64x128, block 128 (m32n64 warps), 4 CTAs/SM,
// NBUF=2 (16KB buffers), B-fragment ping-pong.

#define SW64(off) ((off) ^ (((off) >> 3) & 0x30))

__device__ __forceinline__ uint32_t smem_u32(const void* p) {
    uint32_t a;
    asm("{ .reg .u64 t; cvta.to.shared.u64 t, %1; cvt.u32.u64 %0, t; }" : "=r"(a) : "l"(p));
    return a;
}
__device__ __forceinline__ void ldsm_x4(uint32_t* r, uint32_t a) {
    asm volatile("ldmatrix.sync.aligned.m8n8.x4.shared.b16 {%0,%1,%2,%3}, [%4];"
        : "=r"(r[0]), "=r"(r[1]), "=r"(r[2]), "=r"(r[3]) : "r"(a));
}
__device__ __forceinline__ void mma_f16(float* d, const uint32_t* a, const uint32_t* b) {
    asm volatile(
        "mma.sync.aligned.m16n8k16.row.col.f32.f16.f16.f32 "
        "{%0,%1,%2,%3}, {%4,%5,%6,%7}, {%8,%9}, {%0,%1,%2,%3};"
        : "+f"(d[0]), "+f"(d[1]), "+f"(d[2]), "+f"(d[3])
        : "r"(a[0]), "r"(a[1]), "r"(a[2]), "r"(a[3]), "r"(b[0]), "r"(b[1]));
}
__device__ __forceinline__ unsigned packh(__half a, __half b) {
    return ((unsigned)__half_as_ushort(b) << 16) | (unsigned)__half_as_ushort(a);
}
#define CP_ASYNC16(dst, src) \
    asm volatile("cp.async.cg.shared.global [%0], [%1], 16;" :: "r"(dst), "l"(src))
#define CP_COMMIT() asm volatile("cp.async.commit_group;" ::: "memory")
#define CP_WAIT1()  asm volatile("cp.async.wait_group 1;" ::: "memory")

// ---------------- global scratch ----------------
#define ACT_ELEMS (1024 * 64 * 128)
__device__ unsigned short g_hiA[ACT_ELEMS];
__device__ unsigned short g_loA[ACT_ELEMS];
__device__ unsigned short g_hiB[ACT_ELEMS];
__device__ unsigned short g_loB[ACT_ELEMS];
#define WTOTAL 1998848
__device__ unsigned short g_wh_raw[WTOTAL];

// ---------------- weight prep: transpose + convert to fp16 ----------------
__global__ void prep_weights(const float* __restrict__ xf, const float* __restrict__ f1,
                             const float* __restrict__ f2, const float* __restrict__ f3,
                             const float* __restrict__ md, const float* __restrict__ f4,
                             const float* __restrict__ f5, const float* __restrict__ f6,
                             const float* __restrict__ kf)
{
    const int e = blockIdx.x * blockDim.x + threadIdx.x;
    if (e >= WTOTAL) return;
    const int off[10] = {0, 16384, 81920, 212992, 475136, 1523712, 1785856, 1916928, 1982464, WTOTAL};
    int t = 0;
    #pragma unroll
    for (int i = 1; i < 9; i++) if (e >= off[i]) t = i;
    const int K = (t == 0 || t == 4 || t == 8) ? 128 : 256;
    const float* src;
    switch (t) {
        case 0: src = xf; break; case 1: src = f1; break; case 2: src = f2; break;
        case 3: src = f3; break; case 4: src = md; break; case 5: src = f4; break;
        case 6: src = f5; break; case 7: src = f6; break; default: src = kf; break;
    }
    const int local = e - off[t];
    const int per = K * 128;
    const int g = local / per, rem = local % per;
    const int kk = rem >> 7, n = rem & 127;       // src [g][kk][n]
    const int di = off[t] + g * per + n * K + kk; // dst [g][n][kk]
    g_wh_raw[di] = __half_as_ushort(__float2half(src[local]));
}

// ---------------- stage kernel ----------------
// CTA tile 64x128, K chunks of 32, NBUF=2 cp.async double buffer.
// Per buffer: Ah/Al (64x64B = 4KB each) + Wh (128x64B = 8KB) = 16KB.
#define TILE_A   4096
#define TILE_W   8192
#define BUF_BYTES 16384
#define NBUF 2
#define DYN_SMEM  (NBUF * BUF_BYTES)

__global__ __launch_bounds__(128, 4)
void stage_mma(const float* __restrict__ inF,
               const unsigned short* __restrict__ inHi, const unsigned short* __restrict__ inLo,
               const __half* __restrict__ wh,
               const float* __restrict__ bias,
               float* __restrict__ outF, unsigned short* __restrict__ outHi,
               unsigned short* __restrict__ outLo,
               int stage, int p0, int p1, int tpg, int K)
{
    __shared__ int   sOff0[64];
    __shared__ int   sOff1[64];
    __shared__ int   sOutOff[64];
    __shared__ float sBias[128];
    extern __shared__ __align__(16) char dyn[];

    const int tid = threadIdx.x;
    const int lane = tid & 31, wid = tid >> 5;
    const int g    = blockIdx.x / tpg;
    const int tile = blockIdx.x % tpg;

    const size_t gstride = (size_t)K * 128;
    const __half* whg = wh + (size_t)g * gstride;

    // ---- per-row gather/scatter element offsets (proven indexing, 64 rows) ----
    if (tid < 64) {
        const int t = tile * 64 + tid;
        int r0 = 0, r1 = 0, o = 0;
        if (stage == 0 || stage == 4) {
            r0 = t * 128; r1 = r0;
            o  = t * 128;
        } else if (stage == 1) {                  // down
            const int n = t / p1, l = t % p1;
            int nb_in = p0 >> 1; if (nb_in == 0) nb_in = 1;
            r0 = ((n * nb_in + (g >> 1)) * (2 * p1) + 2 * l) * 128;
            r1 = r0 + 128;
            o  = ((n * p0 + g) * p1 + l) * 128;
        } else if (stage == 2) {                  // middle: g = k*8 + x
            const int n = t;
            const int k = g >> 3, x = g & 7;
            r0 = ((n * 8 + k) * 8 + x) * 128; r1 = r0;
            o  = ((n * 8 + x) * 8 + k) * 128;
        } else {                                  // up: g = 2x + j
            const int n = t / p1, l = t % p1;
            const int x = g >> 1, j = g & 1;
            const int nb_in = p0 * 2;
            r0 = ((n * nb_in + 2 * x)     * p1 + l) * 128;
            r1 = ((n * nb_in + 2 * x + 1) * p1 + l) * 128;
            o  = ((n * p0 + x) * (2 * p1) + 2 * l + j) * 128;
        }
        sOff0[tid] = r0; sOff1[tid] = r1; sOutOff[tid] = o;
    }
    {
        const float* bg = bias ? (bias + ((stage >= 1 && stage <= 3) ? g * 128 : 0)) : nullptr;
        sBias[tid]       = bg ? bg[tid] : 0.0f;
        sBias[tid + 64]  = bg ? bg[tid + 64] : 0.0f;
    }
    __syncthreads();

    const uint32_t dynU = smem_u32(dyn);
    const bool f32in  = (stage == 0);
    const int  nk     = K >> 5;                   // chunks of 32

    // ---- issue loads for chunk ch into buffer ch%2 ----
    auto issue_chunk = [&](int ch) {
        if (ch < nk) {
            const int bufo = (ch % NBUF) * BUF_BYTES;
            const int k0 = ch << 5;
            const bool hi_half = (k0 < 128);
            const int  kk = hi_half ? k0 : (k0 - 128);
            if (f32in) {
                // A from fp32 x: 64 rows x 32k = 512 float4 slots (4 iters @128thr)
                char* Ah = dyn + bufo; char* Al = dyn + bufo + TILE_A;
                #pragma unroll
                for (int i = 0; i < 4; i++) {
                    const int s = tid + (i << 7);
                    const int row = s >> 3, q = s & 7;
                    const int off = sOff0[row] + kk + (q << 2);
                    const float4 v = *(const float4*)(inF + off);
                    const __half hx = __float2half(v.x), hy = __float2half(v.y);
                    const __half hz = __float2half(v.z), hw = __float2half(v.w);
                    const __half lx = __float2half(v.x - __half2float(hx));
                    const __half ly = __float2half(v.y - __half2float(hy));
                    const __half lz = __float2half(v.z - __half2float(hz));
                    const __half lw = __float2half(v.w - __half2float(hw));
                    const unsigned sw = SW64((unsigned)(row * 64 + q * 8));
                    *(uint2*)(Ah + sw) = make_uint2(packh(hx, hy), packh(hz, hw));
                    *(uint2*)(Al + sw) = make_uint2(packh(lx, ly), packh(lz, lw));
                }
            } else {
                // A hi/lo via cp.async: 2 planes x 64 rows x 4 x 16B = 512 slots
                const uint32_t AhU = dynU + bufo, AlU = dynU + bufo + TILE_A;
                #pragma unroll
                for (int i = 0; i < 4; i++) {
                    const int s = tid + (i << 7);
                    const int plane = s >> 8, row = (s >> 2) & 63, u = s & 3;
                    const int off = (hi_half ? sOff0[row] : sOff1[row]) + kk + (u << 3);
                    const unsigned short* src = (plane ? inLo : inHi) + off;
                    const uint32_t dst = (plane ? AlU : AhU) + SW64((unsigned)(row * 64 + u * 16));
                    CP_ASYNC16(dst, src);
                }
            }
            // W via cp.async: 128 n-rows x 4 x 16B = 512 slots
            {
                const uint32_t WhU = dynU + bufo + 2 * TILE_A;
                #pragma unroll
                for (int i = 0; i < 4; i++) {
                    const int s = tid + (i << 7);
                    const int n = s >> 2, u = s & 3;
                    const __half* src = whg + (size_t)n * K + k0 + (u << 3);
                    const uint32_t dst = WhU + SW64((unsigned)(n * 64 + u * 16));
                    CP_ASYNC16(dst, src);
                }
            }
        }
        CP_COMMIT();
    };

    // ---- warp tiling: 2x2 warps, each m32 x n64 ----
    const int warpM = wid >> 1, warpN = wid & 1;
    int offA[2], swA[2];
    #pragma unroll
    for (int mt = 0; mt < 2; mt++) {
        const int r = warpM * 32 + mt * 16 + ((lane & 8) ? 8 : 0) + (lane & 7);
        offA[mt] = r * 64; swA[mt] = ((r >> 1) & 3) << 4;
    }
    const int kaddA = (lane & 16) ? 16 : 0;
    int offB[4], swB[4];
    #pragma unroll
    for (int nt2 = 0; nt2 < 4; nt2++) {
        const int n = warpN * 64 + nt2 * 16 + ((lane & 16) ? 8 : 0) + (lane & 7);
        offB[nt2] = n * 64; swB[nt2] = ((n >> 1) & 3) << 4;
    }
    const int kaddB = (lane & 8) ? 16 : 0;

    float c[2][8][4];
    #pragma unroll
    for (int mt = 0; mt < 2; mt++)
        #pragma unroll
        for (int nt = 0; nt < 8; nt++)
            #pragma unroll
            for (int i = 0; i < 4; i++) c[mt][nt][i] = 0.0f;

    // ---- double-buffered mainloop, two syncs per chunk ----
    issue_chunk(0);
    issue_chunk(1);
    for (int ch = 0; ch < nk; ch++) {
        CP_WAIT1();                                // chunk ch's group retired
        __syncthreads();                           // data visible to all warps

        const uint32_t bufU = dynU + (ch % NBUF) * BUF_BYTES;
        const uint32_t AhU = bufU, AlU = bufU + TILE_A;
        const uint32_t WhU = bufU + 2 * TILE_A;
        #pragma unroll
        for (int ks = 0; ks < 2; ks++) {
            const int kb = ks * 32;
            uint32_t ah[2][4], al[2][4];
            ldsm_x4(ah[0], AhU + offA[0] + ((kb + kaddA) ^ swA[0]));
            ldsm_x4(ah[1], AhU + offA[1] + ((kb + kaddA) ^ swA[1]));
            ldsm_x4(al[0], AlU + offA[0] + ((kb + kaddA) ^ swA[0]));
            ldsm_x4(al[1], AlU + offA[1] + ((kb + kaddA) ^ swA[1]));
            // B fragment ping-pong: load nt2+1 before MMAs of nt2
            uint32_t bh[2][4];
            ldsm_x4(bh[0], WhU + offB[0] + ((kb + kaddB) ^ swB[0]));
            #pragma unroll
            for (int nt2 = 0; nt2 < 4; nt2++) {
                const int cur = nt2 & 1, nxt = cur ^ 1;
                if (nt2 < 3) {
                    ldsm_x4(bh[nxt], WhU + offB[nt2 + 1] + ((kb + kaddB) ^ swB[nt2 + 1]));
                }
                float* c00 = c[0][nt2 * 2 + 0];
                float* c01 = c[0][nt2 * 2 + 1];
                float* c10 = c[1][nt2 * 2 + 0];
                float* c11 = c[1][nt2 * 2 + 1];
                // term Ah*W — 4 independent chains, round-robin
                mma_f16(c00, ah[0], bh[cur] + 0); mma_f16(c01, ah[0], bh[cur] + 2);
                mma_f16(c10, ah[1], bh[cur] + 0); mma_f16(c11, ah[1], bh[cur] + 2);
                // term Al*W
                mma_f16(c00, al[0], bh[cur] + 0); mma_f16(c01, al[0], bh[cur] + 2);
                mma_f16(c10, al[1], bh[cur] + 0); mma_f16(c11, al[1], bh[cur] + 2);
            }
        }
        __syncthreads();                           // all warps done reading buf ch%2
        issue_chunk(ch + 2);                       // safe to overwrite it now
    }

    // ---- epilogue: bias + relu, scatter (fp16 hi/lo planes or fp32 final) ----
    const bool doRelu = (stage != 4);
    const bool f32out = (stage == 4);
    #pragma unroll
    for (int mt = 0; mt < 2; mt++) {
        const int rbase = warpM * 32 + mt * 16 + (lane >> 2);
        #pragma unroll
        for (int h = 0; h < 2; h++) {
            const int off = sOutOff[rbase + h * 8];
            #pragma unroll
            for (int nt = 0; nt < 8; nt++) {
                const int col = warpN * 64 + nt * 8 + 2 * (lane & 3);
                float v0 = c[mt][nt][h * 2 + 0] + sBias[col];
                float v1 = c[mt][nt][h * 2 + 1] + sBias[col + 1];
                if (doRelu) { v0 = fmaxf(v0, 0.0f); v1 = fmaxf(v1, 0.0f); }
                if (f32out) {
                    float2 v; v.x = v0; v.y = v1;
                    *(float2*)(outF + off + col) = v;
                } else {
                    const __half h0 = __float2half(v0);
                    const __half h1 = __float2half(v1);
                    const __half l0 = __float2half(v0 - __half2float(h0));
                    const __half l1 = __float2half(v1 - __half2float(h1));
                    *(unsigned*)(outHi + off + col) = packh(h0, h1);
                    *(unsigned*)(outLo + off + col) = packh(l0, l1);
                }
            }
        }
    }
}

// ---------------- launch ----------------
extern "C" void kernel_launch(void* const* d_in, const int* in_sizes, int n_in,
                              void* d_out, int out_size)
{
    (void)in_sizes; (void)n_in; (void)out_size;
    const float* x  = (const float*)d_in[0];
    const float* xf = (const float*)d_in[1];
    const float* xb = (const float*)d_in[2];
    const float* f1 = (const float*)d_in[3];
    const float* b1 = (const float*)d_in[4];
    const float* f2 = (const float*)d_in[5];
    const float* b2 = (const float*)d_in[6];
    const float* f3 = (const float*)d_in[7];
    const float* b3 = (const float*)d_in[8];
    const float* md = (const float*)d_in[9];
    const float* mb = (const float*)d_in[10];
    const float* f4 = (const float*)d_in[11];
    const float* b4 = (const float*)d_in[12];
    const float* f5 = (const float*)d_in[13];
    const float* b5 = (const float*)d_in[14];
    const float* f6 = (const float*)d_in[15];
    const float* b6 = (const float*)d_in[16];
    const float* kf = (const float*)d_in[17];
    float* out = (float*)d_out;

    unsigned short *hA, *lA, *hB, *lB, *whR;
    cudaGetSymbolAddress((void**)&hA, g_hiA);
    cudaGetSymbolAddress((void**)&lA, g_loA);
    cudaGetSymbolAddress((void**)&hB, g_hiB);
    cudaGetSymbolAddress((void**)&lB, g_loB);
    cudaGetSymbolAddress((void**)&whR, g_wh_raw);
    const __half* whi = (const __half*)whR;

    cudaFuncSetAttribute(stage_mma, cudaFuncAttributeMaxDynamicSharedMemorySize, DYN_SMEM);

    prep_weights<<<(WTOTAL + 255) / 256, 256>>>(xf, f1, f2, f3, md, f4, f5, f6, kf);

    const int Oxf = 0, Of1 = 16384, Of2 = 81920, Of3 = 212992, Omd = 475136,
              Of4 = 1523712, Of5 = 1785856, Of6 = 1916928, Okf = 1982464;

    const dim3 grid(1024), block(128);
    // (inF, inHi, inLo, wh, bias, outF, outHi, outLo, stage, p0, p1, tpg, K)
    stage_mma<<<grid, block, DYN_SMEM>>>(x, nullptr, nullptr, whi + Oxf, xb,
                                         nullptr, hA, lA, 0, 0, 0, 1024, 128);
    stage_mma<<<grid, block, DYN_SMEM>>>(nullptr, hA, lA, whi + Of1, b1,
                                         nullptr, hB, lB, 1, 2, 32, 512, 256);
    stage_mma<<<grid, block, DYN_SMEM>>>(nullptr, hB, lB, whi + Of2, b2,
                                         nullptr, hA, lA, 1, 4, 16, 256, 256);
    stage_mma<<<grid, block, DYN_SMEM>>>(nullptr, hA, lA, whi + Of3, b3,
                                         nullptr, hB, lB, 1, 8, 8, 128, 256);
    stage_mma<<<grid, block, DYN_SMEM>>>(nullptr, hB, lB, whi + Omd, mb,
                                         nullptr, hA, lA, 2, 0, 0, 16, 128);
    stage_mma<<<grid, block, DYN_SMEM>>>(nullptr, hA, lA, whi + Of4, b4,
                                         nullptr, hB, lB, 3, 4, 8, 128, 256);
    stage_mma<<<grid, block, DYN_SMEM>>>(nullptr, hB, lB, whi + Of5, b5,
                                         nullptr, hA, lA, 3, 2, 16, 256, 256);
    stage_mma<<<grid, block, DYN_SMEM>>>(nullptr, hA, lA, whi + Of6, b6,
                                         nullptr, hB, lB, 3, 1, 32, 512, 256);
    stage_mma<<<grid, block, DYN_SMEM>>>(nullptr, hB, lB, whi + Okf, nullptr,
                                         out, nullptr, nullptr, 4, 0, 0, 1024, 128);
}